// round 1
// baseline (speedup 1.0000x reference)
#include <cuda_runtime.h>

#define HIDDEN 1024
#define HEADS 16
#define HD 64
#define NVID 2048
#define NACT 16
#define NTOT 2064
#define BSZ 2
#define BH (BSZ*HEADS)
#define ATT_SCALE 0.125f

// ---------------- scratch (device globals; no allocation allowed) ----------------
__device__ float g_q[BH * NTOT * HD];
__device__ float g_k[BH * NTOT * HD];
__device__ float g_v[BH * NTOT * HD];
__device__ float g_ctx[BSZ * NTOT * HIDDEN];

// ---------------- f32x2 packed-FMA helpers (Blackwell FFMA2) ----------------
union F2 { unsigned long long u; float2 f; };

__device__ __forceinline__ unsigned long long ffma2(unsigned long long a,
                                                    unsigned long long b,
                                                    unsigned long long c) {
    unsigned long long d;
    asm("fma.rn.f32x2 %0, %1, %2, %3;" : "=l"(d) : "l"(a), "l"(b), "l"(c));
    return d;
}
__device__ __forceinline__ unsigned long long pack2(float x, float y) {
    unsigned long long r;
    asm("mov.b64 %0, {%1, %2};" : "=l"(r) : "f"(x), "f"(y));
    return r;
}

// ---------------- GEMM: C[m,n] = sum_k A[m,k] * W[n,k] + bias[n] ----------------
// A row-major [M,1024], W row-major [1024,1024] (both K-contiguous -> NT gemm).
// MODE 0: C row-major [M,1024] (plus per-z base offsets)
// MODE 1: scatter to qkv video layout [B,H,NTOT,HD], m = b*2048+n
// MODE 2: scatter to qkv action layout, m = b*16+i, n = 2048+i
template <int MODE>
__global__ __launch_bounds__(256)
void gemm_nt(const float* __restrict__ A, long long strideAz, int M,
             const float* __restrict__ W, const float* __restrict__ bias,
             float* __restrict__ C, long long strideCz)
{
    __shared__ float As[8][128];
    __shared__ float Ws[8][128];

    const int tid = threadIdx.x;
    const float* Ab = A + (long long)blockIdx.z * strideAz;
    float* Cb = C + (long long)blockIdx.z * strideCz;
    const int rowTile = blockIdx.y * 128;
    const int colTile = blockIdx.x * 128;
    const int lr = tid >> 1;          // 0..127
    const int lc = (tid & 1) * 4;     // 0 or 4
    const int ty = tid >> 4;          // 0..15
    const int tx = tid & 15;          // 0..15

    F2 acc[4][8];
#pragma unroll
    for (int i = 0; i < 4; i++)
#pragma unroll
        for (int j = 0; j < 8; j++) acc[i][j].u = 0ull;

    for (int k0 = 0; k0 < 1024; k0 += 8) {
        float4 av = make_float4(0.f, 0.f, 0.f, 0.f);
        const int am = rowTile + lr;
        if (am < M) av = *(const float4*)(Ab + (long long)am * 1024 + k0 + lc);
        const float4 wv = *(const float4*)(W + (long long)(colTile + lr) * 1024 + k0 + lc);
        __syncthreads();
        As[lc + 0][lr] = av.x; As[lc + 1][lr] = av.y;
        As[lc + 2][lr] = av.z; As[lc + 3][lr] = av.w;
        Ws[lc + 0][lr] = wv.x; Ws[lc + 1][lr] = wv.y;
        Ws[lc + 2][lr] = wv.z; Ws[lc + 3][lr] = wv.w;
        __syncthreads();
#pragma unroll
        for (int k = 0; k < 8; k++) {
            union { float4 v; unsigned long long u[2]; } a0, a1, b0, b1;
            a0.v = *(const float4*)&As[k][ty * 8];
            a1.v = *(const float4*)&As[k][ty * 8 + 4];
            b0.v = *(const float4*)&Ws[k][tx * 8];
            b1.v = *(const float4*)&Ws[k][tx * 8 + 4];
            unsigned long long ai[4] = { a0.u[0], a0.u[1], a1.u[0], a1.u[1] };
            float bs[8] = { b0.v.x, b0.v.y, b0.v.z, b0.v.w,
                            b1.v.x, b1.v.y, b1.v.z, b1.v.w };
#pragma unroll
            for (int j = 0; j < 8; j++) {
                const unsigned long long bd = pack2(bs[j], bs[j]);
#pragma unroll
                for (int i2 = 0; i2 < 4; i2++)
                    acc[i2][j].u = ffma2(ai[i2], bd, acc[i2][j].u);
            }
        }
    }

#pragma unroll
    for (int i2 = 0; i2 < 4; i2++) {
#pragma unroll
        for (int j = 0; j < 8; j++) {
            const int n = colTile + tx * 8 + j;
            const float bv = bias[n];
#pragma unroll
            for (int p = 0; p < 2; p++) {
                const int m = rowTile + ty * 8 + i2 * 2 + p;
                if (m >= M) continue;
                const float val = (p == 0 ? acc[i2][j].f.x : acc[i2][j].f.y) + bv;
                if (MODE == 0) {
                    Cb[(long long)m * 1024 + n] = val;
                } else if (MODE == 1) {
                    const int b_ = m >> 11, nn = m & 2047, h = n >> 6, d = n & 63;
                    Cb[(((long long)(b_ * HEADS + h)) * NTOT + nn) * HD + d] = val;
                } else {
                    const int b_ = m >> 4, h = n >> 6, d = n & 63;
                    const int nn = NVID + (m & 15);
                    Cb[(((long long)(b_ * HEADS + h)) * NTOT + nn) * HD + d] = val;
                }
            }
        }
    }
}

// ---------------- RoPE (video tokens only; action positions are all 0 => identity) ----
__global__ void rope_kernel(float* __restrict__ q, float* __restrict__ k)
{
    const int TOT = BH * NVID * 30;   // 30 rotated pairs per token
    int idx = blockIdx.x * blockDim.x + threadIdx.x;
    if (idx >= TOT) return;
    const int j = idx % 30;
    const int rest = idx / 30;
    const int n = rest & (NVID - 1);
    const int bh = rest >> 11;
    const int seg = j / 10, jj = j - seg * 10;
    const int pos = (seg == 0) ? (n >> 8) : (seg == 1 ? ((n >> 4) & 15) : (n & 15));
    const float omega = expf(-(float)jj * 0.1f * 9.210340371976184f); // ln(10000)
    const float ang = (float)pos * omega;
    float s, c;
    sincosf(ang, &s, &c);
    const long long base = ((long long)bh * NTOT + n) * HD + seg * 20 + 2 * jj;
    float x1 = q[base], x2 = q[base + 1];
    q[base]     = x1 * c - x2 * s;
    q[base + 1] = x2 * c + x1 * s;
    x1 = k[base]; x2 = k[base + 1];
    k[base]     = x1 * c - x2 * s;
    k[base + 1] = x2 * c + x1 * s;
}

// ---------------- flash attention: 64x64 tiles, online softmax ----------------
// grid: (33 q-tiles, 32 b*h). Output written directly into [B, N, HIDDEN] layout.
#define STR 68   // padded smem row stride (floats)
#define ATTN_SMEM_BYTES ((4 * 64 * STR + 3 * 64) * 4)

__global__ __launch_bounds__(256)
void attn_kernel(const float* __restrict__ Q, const float* __restrict__ K,
                 const float* __restrict__ V, float* __restrict__ ctx)
{
    extern __shared__ float smem[];
    float* sQ   = smem;                 // [64][STR]
    float* sKt  = sQ  + 64 * STR;       // [64 dims][STR keys]  (transposed K)
    float* sV   = sKt + 64 * STR;       // [64 keys][STR dims]
    float* sS   = sV  + 64 * STR;       // [64][STR]
    float* rowM = sS  + 64 * STR;
    float* rowL = rowM + 64;
    float* rowC = rowL + 64;

    const int tid = threadIdx.x;
    const int qt = blockIdx.x;
    const int bh = blockIdx.y;
    const int b = bh >> 4, h = bh & 15;
    const long long base = (long long)bh * NTOT * HD;
    const int ty = tid >> 4, tx = tid & 15;

    // load Q tile (zero-fill out-of-range rows)
#pragma unroll
    for (int t = 0; t < 4; t++) {
        const int lin = tid + t * 256;
        const int row = lin >> 4, c4 = (lin & 15) * 4;
        const int n = qt * 64 + row;
        float4 qv = make_float4(0.f, 0.f, 0.f, 0.f);
        if (n < NTOT) qv = *(const float4*)(Q + base + (long long)n * HD + c4);
        *(float4*)&sQ[row * STR + c4] = qv;
    }
    if (tid < 64) { rowM[tid] = -1e30f; rowL[tid] = 0.f; }

    F2 o2[4][2];
#pragma unroll
    for (int i = 0; i < 4; i++) { o2[i][0].u = 0ull; o2[i][1].u = 0ull; }

    const int NKT = (NTOT + 63) / 64;   // 33
    for (int kt = 0; kt < NKT; kt++) {
        __syncthreads();   // prev iteration's PV done before refilling K/V
        // load K (transposed into sKt) and V
#pragma unroll
        for (int t = 0; t < 4; t++) {
            const int lin = tid + t * 256;
            const int row = lin >> 4, c4 = (lin & 15) * 4;
            const int key = kt * 64 + row;
            float4 kv = make_float4(0.f, 0.f, 0.f, 0.f);
            float4 vv = make_float4(0.f, 0.f, 0.f, 0.f);
            if (key < NTOT) {
                kv = *(const float4*)(K + base + (long long)key * HD + c4);
                vv = *(const float4*)(V + base + (long long)key * HD + c4);
            }
            sKt[(c4 + 0) * STR + row] = kv.x;
            sKt[(c4 + 1) * STR + row] = kv.y;
            sKt[(c4 + 2) * STR + row] = kv.z;
            sKt[(c4 + 3) * STR + row] = kv.w;
            *(float4*)&sV[row * STR + c4] = vv;
        }
        __syncthreads();

        // S = Q K^T  (thread owns rows ty*4+i, cols tx*4..tx*4+3; f32x2 over col pairs)
        F2 acc[4][2];
#pragma unroll
        for (int i = 0; i < 4; i++) { acc[i][0].u = 0ull; acc[i][1].u = 0ull; }
        for (int kk = 0; kk < 64; kk += 4) {
            union { float4 v; float s[4]; } q4[4];
#pragma unroll
            for (int i = 0; i < 4; i++)
                q4[i].v = *(const float4*)&sQ[(ty * 4 + i) * STR + kk];
#pragma unroll
            for (int m = 0; m < 4; m++) {
                union { float4 v; unsigned long long u[2]; } kt4;
                kt4.v = *(const float4*)&sKt[(kk + m) * STR + tx * 4];
#pragma unroll
                for (int i = 0; i < 4; i++) {
                    const unsigned long long qd = pack2(q4[i].s[m], q4[i].s[m]);
                    acc[i][0].u = ffma2(qd, kt4.u[0], acc[i][0].u);
                    acc[i][1].u = ffma2(qd, kt4.u[1], acc[i][1].u);
                }
            }
        }
        const int kvalid = NTOT - kt * 64;
#pragma unroll
        for (int i = 0; i < 4; i++) {
            float4 sv;
            sv.x = acc[i][0].f.x * ATT_SCALE;
            sv.y = acc[i][0].f.y * ATT_SCALE;
            sv.z = acc[i][1].f.x * ATT_SCALE;
            sv.w = acc[i][1].f.y * ATT_SCALE;
            const int c0 = tx * 4;
            if (c0 + 0 >= kvalid) sv.x = -1e30f;
            if (c0 + 1 >= kvalid) sv.y = -1e30f;
            if (c0 + 2 >= kvalid) sv.z = -1e30f;
            if (c0 + 3 >= kvalid) sv.w = -1e30f;
            *(float4*)&sS[(ty * 4 + i) * STR + tx * 4] = sv;
        }
        __syncthreads();

        // online softmax: row r = tid>>2, 4 threads per row, shuffle-reduce
        {
            const int r = tid >> 2, g = tid & 3;
            float* srow = &sS[r * STR + g * 16];
            float lmax = -1e30f;
#pragma unroll
            for (int u = 0; u < 16; u++) lmax = fmaxf(lmax, srow[u]);
            lmax = fmaxf(lmax, __shfl_xor_sync(0xffffffffu, lmax, 1));
            lmax = fmaxf(lmax, __shfl_xor_sync(0xffffffffu, lmax, 2));
            const float mold = rowM[r];
            const float mnew = fmaxf(mold, lmax);
            const float corr = __expf(mold - mnew);
            float lsum = 0.f;
#pragma unroll
            for (int u = 0; u < 16; u++) {
                const float p = __expf(srow[u] - mnew);
                srow[u] = p;
                lsum += p;
            }
            lsum += __shfl_xor_sync(0xffffffffu, lsum, 1);
            lsum += __shfl_xor_sync(0xffffffffu, lsum, 2);
            if (g == 0) {
                rowM[r] = mnew;
                rowL[r] = rowL[r] * corr + lsum;
                rowC[r] = corr;
            }
        }
        __syncthreads();

        // O = O*corr + P V
#pragma unroll
        for (int i = 0; i < 4; i++) {
            const float c = rowC[ty * 4 + i];
            o2[i][0].f.x *= c; o2[i][0].f.y *= c;
            o2[i][1].f.x *= c; o2[i][1].f.y *= c;
        }
        for (int kk = 0; kk < 64; kk += 4) {
            union { float4 v; float s[4]; } p4[4];
#pragma unroll
            for (int i = 0; i < 4; i++)
                p4[i].v = *(const float4*)&sS[(ty * 4 + i) * STR + kk];
#pragma unroll
            for (int m = 0; m < 4; m++) {
                union { float4 v; unsigned long long u[2]; } v4;
                v4.v = *(const float4*)&sV[(kk + m) * STR + tx * 4];
#pragma unroll
                for (int i = 0; i < 4; i++) {
                    const unsigned long long pd = pack2(p4[i].s[m], p4[i].s[m]);
                    o2[i][0].u = ffma2(pd, v4.u[0], o2[i][0].u);
                    o2[i][1].u = ffma2(pd, v4.u[1], o2[i][1].u);
                }
            }
        }
    }

    // normalize + write ctx in [B, N, HIDDEN] layout
#pragma unroll
    for (int i = 0; i < 4; i++) {
        const int row = ty * 4 + i;
        const int n = qt * 64 + row;
        if (n < NTOT) {
            const float invl = 1.0f / rowL[row];
            float4 ov;
            ov.x = o2[i][0].f.x * invl;
            ov.y = o2[i][0].f.y * invl;
            ov.z = o2[i][1].f.x * invl;
            ov.w = o2[i][1].f.y * invl;
            *(float4*)(ctx + ((long long)b * NTOT + n) * HIDDEN + h * HD + tx * 4) = ov;
        }
    }
}

// ---------------- host launcher ----------------
extern "C" void kernel_launch(void* const* d_in, const int* in_sizes, int n_in,
                              void* d_out, int out_size)
{
    (void)out_size;
    const float* video = nullptr;
    const float* action = nullptr;
    const float* wb[16];
    int wi = 0;
    for (int i = 0; i < n_in; i++) {
        const int sz = in_sizes[i];
        if (sz == BSZ * NVID * HIDDEN)       video  = (const float*)d_in[i];
        else if (sz == BSZ * NACT * HIDDEN)  action = (const float*)d_in[i];
        else if (wi < 16)                    wb[wi++] = (const float*)d_in[i];
    }
    // order: W_q,b_q, W_k,b_k, W_v,b_v, W_qa,b_qa, W_ka,b_ka, W_va,b_va, W_proj,b_proj, W_proj_a,b_proj_a
    float* out = (float*)d_out;

    float *qp, *kp, *vp, *cp;
    cudaGetSymbolAddress((void**)&qp, g_q);
    cudaGetSymbolAddress((void**)&kp, g_k);
    cudaGetSymbolAddress((void**)&vp, g_v);
    cudaGetSymbolAddress((void**)&cp, g_ctx);

    const dim3 blk(256);

    // QKV projections (video)
    const dim3 gv(8, 32, 1);
    gemm_nt<1><<<gv, blk>>>(video, 0, BSZ * NVID, wb[0], wb[1], qp, 0);
    gemm_nt<1><<<gv, blk>>>(video, 0, BSZ * NVID, wb[2], wb[3], kp, 0);
    gemm_nt<1><<<gv, blk>>>(video, 0, BSZ * NVID, wb[4], wb[5], vp, 0);

    // QKV projections (action)
    const dim3 ga(8, 1, 1);
    gemm_nt<2><<<ga, blk>>>(action, 0, BSZ * NACT, wb[6],  wb[7],  qp, 0);
    gemm_nt<2><<<ga, blk>>>(action, 0, BSZ * NACT, wb[8],  wb[9],  kp, 0);
    gemm_nt<2><<<ga, blk>>>(action, 0, BSZ * NACT, wb[10], wb[11], vp, 0);

    // RoPE on video q/k (action positions are all zero -> identity)
    const int tot = BH * NVID * 30;
    rope_kernel<<<(tot + 255) / 256, 256>>>(qp, kp);

    // attention
    cudaFuncSetAttribute(attn_kernel, cudaFuncAttributeMaxDynamicSharedMemorySize,
                         ATTN_SMEM_BYTES);
    attn_kernel<<<dim3(33, 32), 256, ATTN_SMEM_BYTES>>>(qp, kp, vp, cp);

    // output projections: video rows then action rows (z = batch)
    gemm_nt<0><<<dim3(8, 16, 2), blk>>>(cp, (long long)NTOT * HIDDEN, NVID,
                                        wb[12], wb[13],
                                        out, (long long)NVID * HIDDEN);
    gemm_nt<0><<<dim3(8, 1, 2), blk>>>(cp + (long long)NVID * HIDDEN,
                                       (long long)NTOT * HIDDEN, NACT,
                                       wb[14], wb[15],
                                       out + (long long)BSZ * NVID * HIDDEN,
                                       (long long)NACT * HIDDEN);
}

// round 2
// speedup vs baseline: 1.3270x; 1.3270x over previous
#include <cuda_runtime.h>
#include <cstdint>

#define HIDDEN 1024
#define HEADS 16
#define HD 64
#define NVID 2048
#define NACT 16
#define NTOT 2064
#define BSZ 2
#define BH (BSZ*HEADS)
#define ATT_SCALE 0.125f

// ---------------- scratch (device globals; no allocation allowed) ----------------
__device__ float g_q[BH * NTOT * HD];
__device__ float g_k[BH * NTOT * HD];
__device__ float g_v[BH * NTOT * HD];
__device__ float g_ctx[BSZ * NTOT * HIDDEN];

// ---------------- f32x2 packed-FMA helpers (Blackwell FFMA2) ----------------
union F2 { unsigned long long u; float2 f; };
union Fl4 { float4 v; float s[4]; unsigned long long u[2]; };

__device__ __forceinline__ unsigned long long ffma2(unsigned long long a,
                                                    unsigned long long b,
                                                    unsigned long long c) {
    unsigned long long d;
    asm("fma.rn.f32x2 %0, %1, %2, %3;" : "=l"(d) : "l"(a), "l"(b), "l"(c));
    return d;
}
__device__ __forceinline__ unsigned long long pack2(float x, float y) {
    unsigned long long r;
    asm("mov.b64 %0, {%1, %2};" : "=l"(r) : "f"(x), "f"(y));
    return r;
}
__device__ __forceinline__ void cpa16(void* s, const void* g) {
    uint32_t sa = (uint32_t)__cvta_generic_to_shared(s);
    asm volatile("cp.async.cg.shared.global [%0], [%1], 16;" :: "r"(sa), "l"(g) : "memory");
}
__device__ __forceinline__ void cp_commit() {
    asm volatile("cp.async.commit_group;" ::: "memory");
}
__device__ __forceinline__ void cp_wait0() {
    asm volatile("cp.async.wait_group 0;" ::: "memory");
}

// ---------------- shared GEMM core: 128x128 tile, K=1024 ----------------
// acc[i2][j]: rows rowTile + ty*8 + i2*2 + {0,1}, cols colTile + tx*8 + j
__device__ __forceinline__ void gemm_core(const float* __restrict__ A, int M,
                                          const float* __restrict__ W,
                                          int rowTile, int colTile,
                                          F2 (&acc)[4][8])
{
    __shared__ float As[8][128];
    __shared__ float Ws[8][128];

    const int tid = threadIdx.x;
    const int lr = tid >> 1;          // 0..127
    const int lc = (tid & 1) * 4;     // 0 or 4
    const int ty = tid >> 4;          // 0..15
    const int tx = tid & 15;          // 0..15

#pragma unroll
    for (int i = 0; i < 4; i++)
#pragma unroll
        for (int j = 0; j < 8; j++) acc[i][j].u = 0ull;

    for (int k0 = 0; k0 < 1024; k0 += 8) {
        float4 av = make_float4(0.f, 0.f, 0.f, 0.f);
        const int am = rowTile + lr;
        if (am < M) av = *(const float4*)(A + (long long)am * 1024 + k0 + lc);
        const float4 wv = *(const float4*)(W + (long long)(colTile + lr) * 1024 + k0 + lc);
        __syncthreads();
        As[lc + 0][lr] = av.x; As[lc + 1][lr] = av.y;
        As[lc + 2][lr] = av.z; As[lc + 3][lr] = av.w;
        Ws[lc + 0][lr] = wv.x; Ws[lc + 1][lr] = wv.y;
        Ws[lc + 2][lr] = wv.z; Ws[lc + 3][lr] = wv.w;
        __syncthreads();
#pragma unroll
        for (int k = 0; k < 8; k++) {
            Fl4 a0, a1, b0, b1;
            a0.v = *(const float4*)&As[k][ty * 8];
            a1.v = *(const float4*)&As[k][ty * 8 + 4];
            b0.v = *(const float4*)&Ws[k][tx * 8];
            b1.v = *(const float4*)&Ws[k][tx * 8 + 4];
            unsigned long long ai[4] = { a0.u[0], a0.u[1], a1.u[0], a1.u[1] };
            float bs[8] = { b0.s[0], b0.s[1], b0.s[2], b0.s[3],
                            b1.s[0], b1.s[1], b1.s[2], b1.s[3] };
#pragma unroll
            for (int j = 0; j < 8; j++) {
                const unsigned long long bd = pack2(bs[j], bs[j]);
#pragma unroll
                for (int i2 = 0; i2 < 4; i2++)
                    acc[i2][j].u = ffma2(ai[i2], bd, acc[i2][j].u);
            }
        }
    }
}

// ---------------- fused QKV projection (video + action tiles) ----------------
// grid (8, 33, 3): z = {q,k,v}; by<32 -> video rows; by==32 -> action rows (free wave slot)
__global__ __launch_bounds__(256)
void gemm_qkv(const float* __restrict__ video, const float* __restrict__ action,
              const float* __restrict__ wq, const float* __restrict__ bq,
              const float* __restrict__ wk, const float* __restrict__ bk,
              const float* __restrict__ wv, const float* __restrict__ bv,
              const float* __restrict__ wqa, const float* __restrict__ bqa,
              const float* __restrict__ wka, const float* __restrict__ bka,
              const float* __restrict__ wva, const float* __restrict__ bva,
              float* __restrict__ qp, float* __restrict__ kp, float* __restrict__ vp)
{
    const int z = blockIdx.z;
    const bool act = (blockIdx.y == 32);
    const float* A = act ? action : video;
    const int M = act ? (BSZ * NACT) : (BSZ * NVID);
    const int rowTile = act ? 0 : blockIdx.y * 128;
    const int colTile = blockIdx.x * 128;

    const float* W;
    const float* bias;
    float* out;
    if (z == 0) { out = qp; W = act ? wqa : wq; bias = act ? bqa : bq; }
    else if (z == 1) { out = kp; W = act ? wka : wk; bias = act ? bka : bk; }
    else { out = vp; W = act ? wva : wv; bias = act ? bva : bv; }

    F2 acc[4][8];
    gemm_core(A, M, W, rowTile, colTile, acc);

    const int ty = threadIdx.x >> 4, tx = threadIdx.x & 15;
#pragma unroll
    for (int i2 = 0; i2 < 4; i2++) {
#pragma unroll
        for (int j = 0; j < 8; j++) {
            const int n = colTile + tx * 8 + j;
            const float bvv = bias[n];
#pragma unroll
            for (int p = 0; p < 2; p++) {
                const int m = rowTile + ty * 8 + i2 * 2 + p;
                if (m >= M) continue;
                const float val = (p == 0 ? acc[i2][j].f.x : acc[i2][j].f.y) + bvv;
                const int h = n >> 6, d = n & 63;
                int b_, nn;
                if (!act) { b_ = m >> 11; nn = m & 2047; }
                else { b_ = m >> 4; nn = NVID + (m & 15); }
                out[(((long long)(b_ * HEADS + h)) * NTOT + nn) * HD + d] = val;
            }
        }
    }
}

// ---------------- fused output projection ----------------
// grid (8, 17, 2): z = batch; by<16 -> video rows; by==16 -> action rows
__global__ __launch_bounds__(256)
void gemm_out(const float* __restrict__ ctx,
              const float* __restrict__ wp, const float* __restrict__ bp,
              const float* __restrict__ wpa, const float* __restrict__ bpa,
              float* __restrict__ dout)
{
    const int z = blockIdx.z;
    const bool act = (blockIdx.y == 16);
    const float* A = ctx + (long long)z * NTOT * HIDDEN + (act ? (long long)NVID * HIDDEN : 0);
    const int M = act ? NACT : NVID;
    const int rowTile = act ? 0 : blockIdx.y * 128;
    const int colTile = blockIdx.x * 128;
    const float* W = act ? wpa : wp;
    const float* bias = act ? bpa : bp;
    float* C = act ? (dout + (long long)BSZ * NVID * HIDDEN + (long long)z * NACT * HIDDEN)
                   : (dout + (long long)z * NVID * HIDDEN);

    F2 acc[4][8];
    gemm_core(A, M, W, rowTile, colTile, acc);

    const int ty = threadIdx.x >> 4, tx = threadIdx.x & 15;
#pragma unroll
    for (int i2 = 0; i2 < 4; i2++) {
#pragma unroll
        for (int j = 0; j < 8; j++) {
            const int n = colTile + tx * 8 + j;
            const float bvv = bias[n];
#pragma unroll
            for (int p = 0; p < 2; p++) {
                const int m = rowTile + ty * 8 + i2 * 2 + p;
                if (m >= M) continue;
                C[(long long)m * 1024 + n] = (p == 0 ? acc[i2][j].f.x : acc[i2][j].f.y) + bvv;
            }
        }
    }
}

// ---------------- RoPE (video tokens only; action positions are all 0 => identity) ----
__global__ void rope_kernel(float* __restrict__ q, float* __restrict__ k)
{
    const int TOT = BH * NVID * 30;   // 30 rotated pairs per token
    int idx = blockIdx.x * blockDim.x + threadIdx.x;
    if (idx >= TOT) return;
    const int j = idx % 30;
    const int rest = idx / 30;
    const int n = rest & (NVID - 1);
    const int bh = rest >> 11;
    const int seg = j / 10, jj = j - seg * 10;
    const int pos = (seg == 0) ? (n >> 8) : (seg == 1 ? ((n >> 4) & 15) : (n & 15));
    const float omega = expf(-(float)jj * 0.1f * 9.210340371976184f); // ln(10000)
    const float ang = (float)pos * omega;
    float s, c;
    sincosf(ang, &s, &c);
    const long long base = ((long long)bh * NTOT + n) * HD + seg * 20 + 2 * jj;
    float x1 = q[base], x2 = q[base + 1];
    q[base]     = x1 * c - x2 * s;
    q[base + 1] = x2 * c + x1 * s;
    x1 = k[base]; x2 = k[base + 1];
    k[base]     = x1 * c - x2 * s;
    k[base + 1] = x2 * c + x1 * s;
}

// ---------------- flash attention: 64x64 tiles, cp.async double-buffered K/V,
// register softmax with shuffle reductions, 2 barriers/tile ----------------
#define STR 68
#define ATTN_SMEM_BYTES (6 * 64 * STR * 4)

__global__ __launch_bounds__(256, 2)
void attn_kernel(const float* __restrict__ Q, const float* __restrict__ K,
                 const float* __restrict__ V, float* __restrict__ ctx)
{
    extern __shared__ float smem[];
    float* sQ  = smem;
    float* sK0 = sQ  + 64 * STR;
    float* sK1 = sK0 + 64 * STR;
    float* sV0 = sK1 + 64 * STR;
    float* sV1 = sV0 + 64 * STR;
    float* sS  = sV1 + 64 * STR;

    const int tid = threadIdx.x;
    const int qt = blockIdx.x;
    const int bh = blockIdx.y;
    const int b = bh >> 4, h = bh & 15;
    const long long base = (long long)bh * NTOT * HD;
    const int ty = tid >> 4, tx = tid & 15;

    // prologue: Q tile + K/V tile 0 via cp.async (tile 0 keys always valid)
#pragma unroll
    for (int t = 0; t < 4; t++) {
        const int lin = tid + t * 256;
        const int row = lin >> 4, c4 = (lin & 15) * 4;
        const int n = qt * 64 + row;
        if (n < NTOT) cpa16(&sQ[row * STR + c4], Q + base + (long long)n * HD + c4);
        cpa16(&sK0[row * STR + c4], K + base + (long long)row * HD + c4);
        cpa16(&sV0[row * STR + c4], V + base + (long long)row * HD + c4);
    }
    cp_commit();

    float rm[4], rl[4];
    F2 o2[4][2];
#pragma unroll
    for (int i = 0; i < 4; i++) {
        rm[i] = -1e30f; rl[i] = 0.f;
        o2[i][0].u = 0ull; o2[i][1].u = 0ull;
    }

    cp_wait0();
    __syncthreads();

    const int NKT = (NTOT + 63) / 64;   // 33
    for (int kt = 0; kt < NKT; kt++) {
        float* sK  = (kt & 1) ? sK1 : sK0;
        float* sV  = (kt & 1) ? sV1 : sV0;
        float* sKn = (kt & 1) ? sK0 : sK1;
        float* sVn = (kt & 1) ? sV0 : sV1;

        // async-prefetch next tile (overlaps with S compute below)
        if (kt + 1 < NKT) {
#pragma unroll
            for (int t = 0; t < 4; t++) {
                const int lin = tid + t * 256;
                const int row = lin >> 4, c4 = (lin & 15) * 4;
                const int key = (kt + 1) * 64 + row;
                if (key < NTOT) {
                    cpa16(&sKn[row * STR + c4], K + base + (long long)key * HD + c4);
                    cpa16(&sVn[row * STR + c4], V + base + (long long)key * HD + c4);
                }
            }
        }
        cp_commit();

        // S = Q K^T : thread owns rows ty*4+i, cols tx+16j (j=0..3)
        F2 acc[4][2];
#pragma unroll
        for (int i = 0; i < 4; i++) { acc[i][0].u = 0ull; acc[i][1].u = 0ull; }
        for (int kk = 0; kk < 64; kk += 4) {
            Fl4 q4[4], k4[4];
#pragma unroll
            for (int i = 0; i < 4; i++)
                q4[i].v = *(const float4*)&sQ[(ty * 4 + i) * STR + kk];
#pragma unroll
            for (int c = 0; c < 4; c++)
                k4[c].v = *(const float4*)&sK[(tx + 16 * c) * STR + kk];
#pragma unroll
            for (int m = 0; m < 4; m++) {
                const unsigned long long kp0 = pack2(k4[0].s[m], k4[1].s[m]);
                const unsigned long long kp1 = pack2(k4[2].s[m], k4[3].s[m]);
#pragma unroll
                for (int i = 0; i < 4; i++) {
                    const unsigned long long qd = pack2(q4[i].s[m], q4[i].s[m]);
                    acc[i][0].u = ffma2(qd, kp0, acc[i][0].u);
                    acc[i][1].u = ffma2(qd, kp1, acc[i][1].u);
                }
            }
        }

        // scale + mask; softmax in registers with shuffle row reductions
        const int kvalid = NTOT - kt * 64;
#pragma unroll
        for (int i = 0; i < 4; i++) {
            float s0 = acc[i][0].f.x * ATT_SCALE;   // col tx
            float s1 = acc[i][0].f.y * ATT_SCALE;   // col tx+16
            float s2 = acc[i][1].f.x * ATT_SCALE;   // col tx+32
            float s3 = acc[i][1].f.y * ATT_SCALE;   // col tx+48
            if (kvalid < 64) {
                if (tx      >= kvalid) s0 = -1e30f;
                if (tx + 16 >= kvalid) s1 = -1e30f;
                if (tx + 32 >= kvalid) s2 = -1e30f;
                if (tx + 48 >= kvalid) s3 = -1e30f;
            }
            float tm = fmaxf(fmaxf(s0, s1), fmaxf(s2, s3));
#pragma unroll
            for (int o = 1; o < 16; o <<= 1)
                tm = fmaxf(tm, __shfl_xor_sync(0xffffffffu, tm, o));
            const float mnew = fmaxf(rm[i], tm);
            const float corr = __expf(rm[i] - mnew);
            rm[i] = mnew;
            const float p0 = __expf(s0 - mnew);
            const float p1 = __expf(s1 - mnew);
            const float p2 = __expf(s2 - mnew);
            const float p3 = __expf(s3 - mnew);
            float ts = (p0 + p1) + (p2 + p3);
#pragma unroll
            for (int o = 1; o < 16; o <<= 1)
                ts += __shfl_xor_sync(0xffffffffu, ts, o);
            rl[i] = rl[i] * corr + ts;
            o2[i][0].f.x *= corr; o2[i][0].f.y *= corr;
            o2[i][1].f.x *= corr; o2[i][1].f.y *= corr;
            float* prow = &sS[(ty * 4 + i) * STR];
            prow[tx] = p0; prow[tx + 16] = p1; prow[tx + 32] = p2; prow[tx + 48] = p3;
        }

        cp_wait0();
        __syncthreads();   // publishes P and next K/V buffers

        // O += P V : thread accumulates dims tx*4 .. tx*4+3 for its 4 rows
        for (int kk = 0; kk < 64; kk += 4) {
            Fl4 p4[4], v4[4];
#pragma unroll
            for (int i = 0; i < 4; i++)
                p4[i].v = *(const float4*)&sS[(ty * 4 + i) * STR + kk];
#pragma unroll
            for (int m = 0; m < 4; m++)
                v4[m].v = *(const float4*)&sV[(kk + m) * STR + tx * 4];
#pragma unroll
            for (int m = 0; m < 4; m++) {
#pragma unroll
                for (int i = 0; i < 4; i++) {
                    const unsigned long long pd = pack2(p4[i].s[m], p4[i].s[m]);
                    o2[i][0].u = ffma2(pd, v4[m].u[0], o2[i][0].u);
                    o2[i][1].u = ffma2(pd, v4[m].u[1], o2[i][1].u);
                }
            }
        }
        __syncthreads();   // protect sS / current K,V from next tile's writes
    }

    // normalize + write ctx in [B, N, HIDDEN] layout
#pragma unroll
    for (int i = 0; i < 4; i++) {
        const int n = qt * 64 + ty * 4 + i;
        if (n < NTOT) {
            const float invl = 1.0f / rl[i];
            float4 ov;
            ov.x = o2[i][0].f.x * invl;
            ov.y = o2[i][0].f.y * invl;
            ov.z = o2[i][1].f.x * invl;
            ov.w = o2[i][1].f.y * invl;
            *(float4*)(ctx + ((long long)b * NTOT + n) * HIDDEN + h * HD + tx * 4) = ov;
        }
    }
}

// ---------------- host launcher ----------------
extern "C" void kernel_launch(void* const* d_in, const int* in_sizes, int n_in,
                              void* d_out, int out_size)
{
    (void)out_size;
    const float* video = nullptr;
    const float* action = nullptr;
    const float* wb[16];
    int wi = 0;
    for (int i = 0; i < n_in; i++) {
        const int sz = in_sizes[i];
        if (sz == BSZ * NVID * HIDDEN)       video  = (const float*)d_in[i];
        else if (sz == BSZ * NACT * HIDDEN)  action = (const float*)d_in[i];
        else if (wi < 16)                    wb[wi++] = (const float*)d_in[i];
    }
    float* out = (float*)d_out;

    float *qp, *kp, *vp, *cp;
    cudaGetSymbolAddress((void**)&qp, g_q);
    cudaGetSymbolAddress((void**)&kp, g_k);
    cudaGetSymbolAddress((void**)&vp, g_v);
    cudaGetSymbolAddress((void**)&cp, g_ctx);

    const dim3 blk(256);

    // fused QKV projections: video (by 0..31) + action (by 32), z = {q,k,v}
    gemm_qkv<<<dim3(8, 33, 3), blk>>>(video, action,
                                      wb[0], wb[1], wb[2], wb[3], wb[4], wb[5],
                                      wb[6], wb[7], wb[8], wb[9], wb[10], wb[11],
                                      qp, kp, vp);

    // RoPE on video q/k (action positions are all zero -> identity)
    const int tot = BH * NVID * 30;
    rope_kernel<<<(tot + 255) / 256, 256>>>(qp, kp);

    // attention
    cudaFuncSetAttribute(attn_kernel, cudaFuncAttributeMaxDynamicSharedMemorySize,
                         ATTN_SMEM_BYTES);
    attn_kernel<<<dim3(33, 32), 256, ATTN_SMEM_BYTES>>>(qp, kp, vp, cp);

    // fused output projection: video (by 0..15) + action (by 16), z = batch
    gemm_out<<<dim3(8, 17, 2), blk>>>(cp, wb[12], wb[13], wb[14], wb[15], out);
}

// round 4
// speedup vs baseline: 1.8164x; 1.3688x over previous
#include <cuda_runtime.h>
#include <cuda_bf16.h>
#include <cstdint>

#define HIDDEN 1024
#define HEADS 16
#define HD 64
#define NVID 2048
#define NACT 16
#define NTOT 2064
#define BSZ 2
#define BH (BSZ*HEADS)
#define ATT_SCALE 0.125f

#define WSZ 1048576LL
#define OFF_VIDEO 0LL
#define OFF_ACTION 4194304LL
#define OFF_W 4227072LL
#define OFF_CTX (OFF_W + 8LL * WSZ)          // 12615680
#define BF_TOTAL (OFF_CTX + 4227072LL)       // 16842752

// ---------------- scratch (device globals; no allocation allowed) ----------------
__device__ float g_q[BH * NTOT * HD];
__device__ float g_k[BH * NTOT * HD];
__device__ float g_v[BH * NTOT * HD];
__device__ float g_ctx[BSZ * NTOT * HIDDEN];
__device__ unsigned short g_bh[BF_TOTAL];    // bf16 hi parts
__device__ unsigned short g_bl[BF_TOTAL];    // bf16 lo parts

// ---------------- helpers ----------------
union F2 { unsigned long long u; float2 f; };
union Fl4 { float4 v; float s[4]; unsigned long long u[2]; };

__device__ __forceinline__ unsigned long long ffma2(unsigned long long a,
                                                    unsigned long long b,
                                                    unsigned long long c) {
    unsigned long long d;
    asm("fma.rn.f32x2 %0, %1, %2, %3;" : "=l"(d) : "l"(a), "l"(b), "l"(c));
    return d;
}
__device__ __forceinline__ unsigned long long pack2(float x, float y) {
    unsigned long long r;
    asm("mov.b64 %0, {%1, %2};" : "=l"(r) : "f"(x), "f"(y));
    return r;
}
__device__ __forceinline__ void cpa16(void* s, const void* g) {
    uint32_t sa = (uint32_t)__cvta_generic_to_shared(s);
    asm volatile("cp.async.cg.shared.global [%0], [%1], 16;" :: "r"(sa), "l"(g) : "memory");
}
__device__ __forceinline__ void cpa16z(uint32_t dst, const void* src, int bytes) {
    asm volatile("cp.async.cg.shared.global [%0], [%1], 16, %2;"
                 :: "r"(dst), "l"(src), "r"(bytes) : "memory");
}
__device__ __forceinline__ void cp_commit() {
    asm volatile("cp.async.commit_group;" ::: "memory");
}
__device__ __forceinline__ void cp_wait0() {
    asm volatile("cp.async.wait_group 0;" ::: "memory");
}
__device__ __forceinline__ uint32_t smem_u32(const void* p) {
    return (uint32_t)__cvta_generic_to_shared(p);
}
__device__ __forceinline__ void ldm4(uint32_t* r, uint32_t addr) {
    asm volatile("ldmatrix.sync.aligned.m8n8.x4.shared.b16 {%0,%1,%2,%3}, [%4];"
                 : "=r"(r[0]), "=r"(r[1]), "=r"(r[2]), "=r"(r[3]) : "r"(addr));
}
__device__ __forceinline__ void mma16816(float* c, const uint32_t* a,
                                         uint32_t b0, uint32_t b1) {
    asm volatile("mma.sync.aligned.m16n8k16.row.col.f32.bf16.bf16.f32 "
                 "{%0,%1,%2,%3}, {%4,%5,%6,%7}, {%8,%9}, {%0,%1,%2,%3};"
                 : "+f"(c[0]), "+f"(c[1]), "+f"(c[2]), "+f"(c[3])
                 : "r"(a[0]), "r"(a[1]), "r"(a[2]), "r"(a[3]), "r"(b0), "r"(b1));
}
__device__ __forceinline__ void bsplit(float x, unsigned short& h, unsigned short& l) {
    __nv_bfloat16 hb = __float2bfloat16_rn(x);
    h = __bfloat16_as_ushort(hb);
    l = __bfloat16_as_ushort(__float2bfloat16_rn(x - __bfloat162float(hb)));
}

// ---------------- fp32 -> bf16 hi/lo split converters ----------------
__global__ void cvt_all(const float* v, const float* a,
                        const float* w0, const float* w1, const float* w2,
                        const float* w3, const float* w4, const float* w5,
                        const float* w6, const float* w7)
{
    const float* srcs[10] = { v, a, w0, w1, w2, w3, w4, w5, w6, w7 };
    const long long offs[10] = { OFF_VIDEO, OFF_ACTION,
        OFF_W + 0 * WSZ, OFF_W + 1 * WSZ, OFF_W + 2 * WSZ, OFF_W + 3 * WSZ,
        OFF_W + 4 * WSZ, OFF_W + 5 * WSZ, OFF_W + 6 * WSZ, OFF_W + 7 * WSZ };
    const int cnts[10] = { 4194304, 32768, 1048576, 1048576, 1048576, 1048576,
                           1048576, 1048576, 1048576, 1048576 };
    const int z = blockIdx.y;
    const float4* src = (const float4*)srcs[z];
    ushort4* hi = (ushort4*)(g_bh + offs[z]);
    ushort4* lo = (ushort4*)(g_bl + offs[z]);
    const int n4 = cnts[z] >> 2;
    for (int i = blockIdx.x * blockDim.x + threadIdx.x; i < n4;
         i += gridDim.x * blockDim.x) {
        const float4 x = src[i];
        ushort4 h, l;
        bsplit(x.x, h.x, l.x); bsplit(x.y, h.y, l.y);
        bsplit(x.z, h.z, l.z); bsplit(x.w, h.w, l.w);
        hi[i] = h; lo[i] = l;
    }
}

__global__ void cvt_ctx()
{
    const float4* src = (const float4*)g_ctx;
    ushort4* hi = (ushort4*)(g_bh + OFF_CTX);
    ushort4* lo = (ushort4*)(g_bl + OFF_CTX);
    const int n4 = (BSZ * NTOT * HIDDEN) >> 2;
    for (int i = blockIdx.x * blockDim.x + threadIdx.x; i < n4;
         i += gridDim.x * blockDim.x) {
        const float4 x = src[i];
        ushort4 h, l;
        bsplit(x.x, h.x, l.x); bsplit(x.y, h.y, l.y);
        bsplit(x.z, h.z, l.z); bsplit(x.w, h.w, l.w);
        hi[i] = h; lo[i] = l;
    }
}

// ================= mma.sync bf16x3 GEMM =================
// CTA: 128x128 tile, K=1024 in 16 chunks of 64 (bf16), double-buffered smem.
// 8 warps 2x4 (M x N); warp tile 64x32; D += Ah*Wh + Ah*Wl + Al*Wh.
#define GT_TILE 16384                 // one bf16 tile: 128 rows * 128 bytes
#define GT_BUF  (4 * GT_TILE)         // Ah, Al, Wh, Wl
#define GT_SMEM (2 * GT_BUF)          // 128 KB

__device__ __forceinline__ void gstage(const unsigned short* Ah, const unsigned short* Al,
                                       int M, int rowTile,
                                       const unsigned short* Wh, const unsigned short* Wl,
                                       int colTile, int k0, uint32_t bufb, int tid)
{
#pragma unroll
    for (int i = 0; i < 16; i++) {
        const int tile = i >> 2;
        const int t = ((i & 3) << 8) + tid;     // 0..1023
        const int row = t >> 3, c = t & 7;
        const uint32_t dst = bufb + tile * GT_TILE + (row << 7) + ((c ^ (row & 7)) << 4);
        if (tile == 0 || tile == 1) {
            const int m = rowTile + row;
            const int mm = (m < M) ? m : 0;
            const unsigned short* s = (tile == 0 ? Ah : Al) + (long long)mm * 1024 + k0 + c * 8;
            cpa16z(dst, s, (m < M) ? 16 : 0);
        } else {
            const unsigned short* s = (tile == 2 ? Wh : Wl) +
                                      (long long)(colTile + row) * 1024 + k0 + c * 8;
            cpa16z(dst, s, 16);
        }
    }
}

// MODE 0: out[m*1024+n]; MODE 1: qkv video scatter; MODE 2: qkv action scatter
template <int MODE>
__device__ __forceinline__ void gemm_body(const unsigned short* Ah, const unsigned short* Al,
                                          int M, int rowTile,
                                          const unsigned short* Wh, const unsigned short* Wl,
                                          int colTile, const float* bias,
                                          float* __restrict__ out)
{
    extern __shared__ char dsmem[];
    const uint32_t sbase = smem_u32(dsmem);
    const int tid = threadIdx.x;
    const int lane = tid & 31, wid = tid >> 5;
    const int warp_m = wid >> 2, warp_n = wid & 3;

    float acc[4][4][4];
#pragma unroll
    for (int a = 0; a < 4; a++)
#pragma unroll
        for (int b = 0; b < 4; b++)
#pragma unroll
            for (int c = 0; c < 4; c++) acc[a][b][c] = 0.f;

    int rA[4], rW[2];
#pragma unroll
    for (int mt = 0; mt < 4; mt++) rA[mt] = warp_m * 64 + mt * 16 + (lane & 15);
#pragma unroll
    for (int nt2 = 0; nt2 < 2; nt2++) rW[nt2] = warp_n * 32 + nt2 * 16 + (lane & 15);
    const int khalf = lane >> 4;

    gstage(Ah, Al, M, rowTile, Wh, Wl, colTile, 0, sbase, tid);
    cp_commit();

    for (int c = 0; c < 16; c++) {
        if (c + 1 < 16) {
            gstage(Ah, Al, M, rowTile, Wh, Wl, colTile, (c + 1) * 64,
                   sbase + ((c + 1) & 1) * GT_BUF, tid);
            cp_commit();
            asm volatile("cp.async.wait_group 1;" ::: "memory");
        } else {
            asm volatile("cp.async.wait_group 0;" ::: "memory");
        }
        __syncthreads();

        const uint32_t bufb = sbase + (c & 1) * GT_BUF;
        const uint32_t sAh = bufb, sAl = bufb + GT_TILE;
        const uint32_t sWh = bufb + 2 * GT_TILE, sWl = bufb + 3 * GT_TILE;

#pragma unroll
        for (int kq = 0; kq < 4; kq++) {
            const int kp = 2 * kq + khalf;
            uint32_t ah[4][4], al[4][4], wh[2][4], wl[2][4];
#pragma unroll
            for (int mt = 0; mt < 4; mt++) {
                const uint32_t off = (rA[mt] << 7) + ((kp ^ (rA[mt] & 7)) << 4);
                ldm4(ah[mt], sAh + off);
                ldm4(al[mt], sAl + off);
            }
#pragma unroll
            for (int nt2 = 0; nt2 < 2; nt2++) {
                const uint32_t off = (rW[nt2] << 7) + ((kp ^ (rW[nt2] & 7)) << 4);
                ldm4(wh[nt2], sWh + off);
                ldm4(wl[nt2], sWl + off);
            }
#pragma unroll
            for (int mt = 0; mt < 4; mt++) {
#pragma unroll
                for (int nt = 0; nt < 4; nt++) {
                    const uint32_t bh0 = wh[nt >> 1][nt & 1], bh1 = wh[nt >> 1][(nt & 1) + 2];
                    const uint32_t bl0 = wl[nt >> 1][nt & 1], bl1 = wl[nt >> 1][(nt & 1) + 2];
                    mma16816(acc[mt][nt], ah[mt], bh0, bh1);
                    mma16816(acc[mt][nt], ah[mt], bl0, bl1);
                    mma16816(acc[mt][nt], al[mt], bh0, bh1);
                }
            }
        }
        __syncthreads();
    }

    // epilogue
    const int g = lane >> 2, tg = lane & 3;
#pragma unroll
    for (int mt = 0; mt < 4; mt++) {
#pragma unroll
        for (int nt = 0; nt < 4; nt++) {
            const int n0 = colTile + warp_n * 32 + nt * 8 + tg * 2;
            const float2 bv = *(const float2*)(bias + n0);
#pragma unroll
            for (int hf = 0; hf < 2; hf++) {
                const int m = rowTile + warp_m * 64 + mt * 16 + g + hf * 8;
                if (m < M) {
                    float2 o;
                    o.x = acc[mt][nt][hf * 2 + 0] + bv.x;
                    o.y = acc[mt][nt][hf * 2 + 1] + bv.y;
                    if (MODE == 0) {
                        *(float2*)(out + (long long)m * 1024 + n0) = o;
                    } else if (MODE == 1) {
                        const int b_ = m >> 11, nn = m & 2047, h = n0 >> 6, d = n0 & 63;
                        *(float2*)(out + (((long long)(b_ * HEADS + h)) * NTOT + nn) * HD + d) = o;
                    } else {
                        const int b_ = m >> 4, h = n0 >> 6, d = n0 & 63;
                        const int nn = NVID + (m & 15);
                        *(float2*)(out + (((long long)(b_ * HEADS + h)) * NTOT + nn) * HD + d) = o;
                    }
                }
            }
        }
    }
}

// grid (8, 33, 3): z = {q,k,v}; by<32 video rows; by==32 action rows
__global__ __launch_bounds__(256, 1)
void gemm_qkv_mma(const float* bq, const float* bk, const float* bv,
                  const float* bqa, const float* bka, const float* bva)
{
    const int z = blockIdx.z;
    const bool act = (blockIdx.y == 32);
    const unsigned short* Ah = g_bh + (act ? OFF_ACTION : OFF_VIDEO);
    const unsigned short* Al = g_bl + (act ? OFF_ACTION : OFF_VIDEO);
    const int M = act ? (BSZ * NACT) : (BSZ * NVID);
    const int rowTile = act ? 0 : blockIdx.y * 128;
    const int colTile = blockIdx.x * 128;
    const int widx = z + (act ? 3 : 0);      // wq,wk,wv / wqa,wka,wva
    const unsigned short* Wh = g_bh + OFF_W + widx * WSZ;
    const unsigned short* Wl = g_bl + OFF_W + widx * WSZ;
    const float* bias = act ? (z == 0 ? bqa : (z == 1 ? bka : bva))
                            : (z == 0 ? bq : (z == 1 ? bk : bv));
    float* out = (z == 0) ? g_q : (z == 1 ? g_k : g_v);
    if (act) gemm_body<2>(Ah, Al, M, rowTile, Wh, Wl, colTile, bias, out);
    else     gemm_body<1>(Ah, Al, M, rowTile, Wh, Wl, colTile, bias, out);
}

// grid (8, 17, 2): z = batch; by<16 video rows; by==16 action rows
__global__ __launch_bounds__(256, 1)
void gemm_out_mma(const float* bp, const float* bpa, float* __restrict__ dout)
{
    const int z = blockIdx.z;
    const bool act = (blockIdx.y == 16);
    const long long aoff = OFF_CTX + (long long)z * NTOT * HIDDEN +
                           (act ? (long long)NVID * HIDDEN : 0);
    const unsigned short* Ah = g_bh + aoff;
    const unsigned short* Al = g_bl + aoff;
    const int M = act ? NACT : NVID;
    const int rowTile = act ? 0 : blockIdx.y * 128;
    const int colTile = blockIdx.x * 128;
    const int widx = act ? 7 : 6;
    const unsigned short* Wh = g_bh + OFF_W + widx * WSZ;
    const unsigned short* Wl = g_bl + OFF_W + widx * WSZ;
    const float* bias = act ? bpa : bp;
    float* C = act ? (dout + (long long)BSZ * NVID * HIDDEN + (long long)z * NACT * HIDDEN)
                   : (dout + (long long)z * NVID * HIDDEN);
    gemm_body<0>(Ah, Al, M, rowTile, Wh, Wl, colTile, bias, C);
}

// ---------------- RoPE (video tokens only; action positions are all 0 => identity) ----
__global__ void rope_kernel(float* __restrict__ q, float* __restrict__ k)
{
    const int TOT = BH * NVID * 30;
    int idx = blockIdx.x * blockDim.x + threadIdx.x;
    if (idx >= TOT) return;
    const int j = idx % 30;
    const int rest = idx / 30;
    const int n = rest & (NVID - 1);
    const int bh = rest >> 11;
    const int seg = j / 10, jj = j - seg * 10;
    const int pos = (seg == 0) ? (n >> 8) : (seg == 1 ? ((n >> 4) & 15) : (n & 15));
    const float omega = expf(-(float)jj * 0.1f * 9.210340371976184f);
    const float ang = (float)pos * omega;
    float s, c;
    sincosf(ang, &s, &c);
    const long long base = ((long long)bh * NTOT + n) * HD + seg * 20 + 2 * jj;
    float x1 = q[base], x2 = q[base + 1];
    q[base]     = x1 * c - x2 * s;
    q[base + 1] = x2 * c + x1 * s;
    x1 = k[base]; x2 = k[base + 1];
    k[base]     = x1 * c - x2 * s;
    k[base + 1] = x2 * c + x1 * s;
}

// ---------------- flash attention (unchanged, known-good) ----------------
#define STR 68
#define ATTN_SMEM_BYTES (6 * 64 * STR * 4)

__global__ __launch_bounds__(256, 2)
void attn_kernel(const float* __restrict__ Q, const float* __restrict__ K,
                 const float* __restrict__ V, float* __restrict__ ctx)
{
    extern __shared__ float smem[];
    float* sQ  = smem;
    float* sK0 = sQ  + 64 * STR;
    float* sK1 = sK0 + 64 * STR;
    float* sV0 = sK1 + 64 * STR;
    float* sV1 = sV0 + 64 * STR;
    float* sS  = sV1 + 64 * STR;

    const int tid = threadIdx.x;
    const int qt = blockIdx.x;
    const int bh = blockIdx.y;
    const int b = bh >> 4, h = bh & 15;
    const long long base = (long long)bh * NTOT * HD;
    const int ty = tid >> 4, tx = tid & 15;

#pragma unroll
    for (int t = 0; t < 4; t++) {
        const int lin = tid + t * 256;
        const int row = lin >> 4, c4 = (lin & 15) * 4;
        const int n = qt * 64 + row;
        if (n < NTOT) cpa16(&sQ[row * STR + c4], Q + base + (long long)n * HD + c4);
        cpa16(&sK0[row * STR + c4], K + base + (long long)row * HD + c4);
        cpa16(&sV0[row * STR + c4], V + base + (long long)row * HD + c4);
    }
    cp_commit();

    float rm[4], rl[4];
    F2 o2[4][2];
#pragma unroll
    for (int i = 0; i < 4; i++) {
        rm[i] = -1e30f; rl[i] = 0.f;
        o2[i][0].u = 0ull; o2[i][1].u = 0ull;
    }

    cp_wait0();
    __syncthreads();

    const int NKT = (NTOT + 63) / 64;
    for (int kt = 0; kt < NKT; kt++) {
        float* sK  = (kt & 1) ? sK1 : sK0;
        float* sV  = (kt & 1) ? sV1 : sV0;
        float* sKn = (kt & 1) ? sK0 : sK1;
        float* sVn = (kt & 1) ? sV0 : sV1;

        if (kt + 1 < NKT) {
#pragma unroll
            for (int t = 0; t < 4; t++) {
                const int lin = tid + t * 256;
                const int row = lin >> 4, c4 = (lin & 15) * 4;
                const int key = (kt + 1) * 64 + row;
                if (key < NTOT) {
                    cpa16(&sKn[row * STR + c4], K + base + (long long)key * HD + c4);
                    cpa16(&sVn[row * STR + c4], V + base + (long long)key * HD + c4);
                }
            }
        }
        cp_commit();

        F2 acc[4][2];
#pragma unroll
        for (int i = 0; i < 4; i++) { acc[i][0].u = 0ull; acc[i][1].u = 0ull; }
        for (int kk = 0; kk < 64; kk += 4) {
            Fl4 q4[4], k4[4];
#pragma unroll
            for (int i = 0; i < 4; i++)
                q4[i].v = *(const float4*)&sQ[(ty * 4 + i) * STR + kk];
#pragma unroll
            for (int c = 0; c < 4; c++)
                k4[c].v = *(const float4*)&sK[(tx + 16 * c) * STR + kk];
#pragma unroll
            for (int m = 0; m < 4; m++) {
                const unsigned long long kp0 = pack2(k4[0].s[m], k4[1].s[m]);
                const unsigned long long kp1 = pack2(k4[2].s[m], k4[3].s[m]);
#pragma unroll
                for (int i = 0; i < 4; i++) {
                    const unsigned long long qd = pack2(q4[i].s[m], q4[i].s[m]);
                    acc[i][0].u = ffma2(qd, kp0, acc[i][0].u);
                    acc[i][1].u = ffma2(qd, kp1, acc[i][1].u);
                }
            }
        }

        const int kvalid = NTOT - kt * 64;
#pragma unroll
        for (int i = 0; i < 4; i++) {
            float s0 = acc[i][0].f.x * ATT_SCALE;
            float s1 = acc[i][0].f.y * ATT_SCALE;
            float s2 = acc[i][1].f.x * ATT_SCALE;
            float s3 = acc[i][1].f.y * ATT_SCALE;
            if (kvalid < 64) {
                if (tx      >= kvalid) s0 = -1e30f;
                if (tx + 16 >= kvalid) s1 = -1e30f;
                if (tx + 32 >= kvalid) s2 = -1e30f;
                if (tx + 48 >= kvalid) s3 = -1e30f;
            }
            float tm = fmaxf(fmaxf(s0, s1), fmaxf(s2, s3));
#pragma unroll
            for (int o = 1; o < 16; o <<= 1)
                tm = fmaxf(tm, __shfl_xor_sync(0xffffffffu, tm, o));
            const float mnew = fmaxf(rm[i], tm);
            const float corr = __expf(rm[i] - mnew);
            rm[i] = mnew;
            const float p0 = __expf(s0 - mnew);
            const float p1 = __expf(s1 - mnew);
            const float p2 = __expf(s2 - mnew);
            const float p3 = __expf(s3 - mnew);
            float ts = (p0 + p1) + (p2 + p3);
#pragma unroll
            for (int o = 1; o < 16; o <<= 1)
                ts += __shfl_xor_sync(0xffffffffu, ts, o);
            rl[i] = rl[i] * corr + ts;
            o2[i][0].f.x *= corr; o2[i][0].f.y *= corr;
            o2[i][1].f.x *= corr; o2[i][1].f.y *= corr;
            float* prow = &sS[(ty * 4 + i) * STR];
            prow[tx] = p0; prow[tx + 16] = p1; prow[tx + 32] = p2; prow[tx + 48] = p3;
        }

        cp_wait0();
        __syncthreads();

        for (int kk = 0; kk < 64; kk += 4) {
            Fl4 p4[4], v4[4];
#pragma unroll
            for (int i = 0; i < 4; i++)
                p4[i].v = *(const float4*)&sS[(ty * 4 + i) * STR + kk];
#pragma unroll
            for (int m = 0; m < 4; m++)
                v4[m].v = *(const float4*)&sV[(kk + m) * STR + tx * 4];
#pragma unroll
            for (int m = 0; m < 4; m++) {
#pragma unroll
                for (int i = 0; i < 4; i++) {
                    const unsigned long long pd = pack2(p4[i].s[m], p4[i].s[m]);
                    o2[i][0].u = ffma2(pd, v4[m].u[0], o2[i][0].u);
                    o2[i][1].u = ffma2(pd, v4[m].u[1], o2[i][1].u);
                }
            }
        }
        __syncthreads();
    }

#pragma unroll
    for (int i = 0; i < 4; i++) {
        const int n = qt * 64 + ty * 4 + i;
        if (n < NTOT) {
            const float invl = 1.0f / rl[i];
            float4 ov;
            ov.x = o2[i][0].f.x * invl;
            ov.y = o2[i][0].f.y * invl;
            ov.z = o2[i][1].f.x * invl;
            ov.w = o2[i][1].f.y * invl;
            *(float4*)(ctx + ((long long)b * NTOT + n) * HIDDEN + h * HD + tx * 4) = ov;
        }
    }
}

// ---------------- host launcher ----------------
extern "C" void kernel_launch(void* const* d_in, const int* in_sizes, int n_in,
                              void* d_out, int out_size)
{
    (void)out_size;
    const float* video = nullptr;
    const float* action = nullptr;
    const float* wb[16];
    int wi = 0;
    for (int i = 0; i < n_in; i++) {
        const int sz = in_sizes[i];
        if (sz == BSZ * NVID * HIDDEN)       video  = (const float*)d_in[i];
        else if (sz == BSZ * NACT * HIDDEN)  action = (const float*)d_in[i];
        else if (wi < 16)                    wb[wi++] = (const float*)d_in[i];
    }
    float* out = (float*)d_out;

    float *qp, *kp, *vp, *cp;
    cudaGetSymbolAddress((void**)&qp, g_q);
    cudaGetSymbolAddress((void**)&kp, g_k);
    cudaGetSymbolAddress((void**)&vp, g_v);
    cudaGetSymbolAddress((void**)&cp, g_ctx);

    cudaFuncSetAttribute(gemm_qkv_mma, cudaFuncAttributeMaxDynamicSharedMemorySize, GT_SMEM);
    cudaFuncSetAttribute(gemm_out_mma, cudaFuncAttributeMaxDynamicSharedMemorySize, GT_SMEM);
    cudaFuncSetAttribute(attn_kernel, cudaFuncAttributeMaxDynamicSharedMemorySize,
                         ATTN_SMEM_BYTES);

    // split inputs + weights into bf16 hi/lo
    cvt_all<<<dim3(1024, 10), 256>>>(video, action, wb[0], wb[2], wb[4], wb[6],
                                     wb[8], wb[10], wb[12], wb[14]);

    // QKV projections on tensor cores (mma.sync bf16x3)
    gemm_qkv_mma<<<dim3(8, 33, 3), 256, GT_SMEM>>>(wb[1], wb[3], wb[5],
                                                   wb[7], wb[9], wb[11]);

    // RoPE on video q/k (action positions are all zero -> identity)
    const int tot = BH * NVID * 30;
    rope_kernel<<<(tot + 255) / 256, 256>>>(qp, kp);

    // attention (FFMA2 flash kernel)
    attn_kernel<<<dim3(33, 32), 256, ATTN_SMEM_BYTES>>>(qp, kp, vp, cp);

    // split ctx, then output projection on tensor cores
    cvt_ctx<<<2048, 256>>>();
    gemm_out_mma<<<dim3(8, 17, 2), 256, GT_SMEM>>>(wb[13], wb[15], out);
}

// round 5
// speedup vs baseline: 1.8183x; 1.0010x over previous
#include <cuda_runtime.h>
#include <cuda_bf16.h>
#include <cstdint>

#define HIDDEN 1024
#define HEADS 16
#define HD 64
#define NVID 2048
#define NACT 16
#define NTOT 2064
#define BSZ 2
#define BH (BSZ*HEADS)
#define ATT_SCALE 0.125f

#define WSZ 1048576LL
#define OFF_VIDEO 0LL
#define OFF_ACTION 4194304LL
#define OFF_W 4227072LL
#define OFF_CTX (OFF_W + 8LL * WSZ)          // 12615680
#define BF_TOTAL (OFF_CTX + 4227072LL)       // 16842752

// ---------------- scratch (device globals; no allocation allowed) ----------------
__device__ float g_q[BH * NTOT * HD];
__device__ float g_k[BH * NTOT * HD];
__device__ float g_v[BH * NTOT * HD];
__device__ float g_ctx[BSZ * NTOT * HIDDEN];
__device__ unsigned short g_bh[BF_TOTAL];    // bf16 hi parts
__device__ unsigned short g_bl[BF_TOTAL];    // bf16 lo parts

// ---------------- helpers ----------------
union F2 { unsigned long long u; float2 f; };
union Fl4 { float4 v; float s[4]; unsigned long long u[2]; };

__device__ __forceinline__ unsigned long long ffma2(unsigned long long a,
                                                    unsigned long long b,
                                                    unsigned long long c) {
    unsigned long long d;
    asm("fma.rn.f32x2 %0, %1, %2, %3;" : "=l"(d) : "l"(a), "l"(b), "l"(c));
    return d;
}
__device__ __forceinline__ unsigned long long pack2(float x, float y) {
    unsigned long long r;
    asm("mov.b64 %0, {%1, %2};" : "=l"(r) : "f"(x), "f"(y));
    return r;
}
__device__ __forceinline__ void cpa16(void* s, const void* g) {
    uint32_t sa = (uint32_t)__cvta_generic_to_shared(s);
    asm volatile("cp.async.cg.shared.global [%0], [%1], 16;" :: "r"(sa), "l"(g) : "memory");
}
__device__ __forceinline__ void cpa16z(uint32_t dst, const void* src, int bytes) {
    asm volatile("cp.async.cg.shared.global [%0], [%1], 16, %2;"
                 :: "r"(dst), "l"(src), "r"(bytes) : "memory");
}
__device__ __forceinline__ void cp_commit() {
    asm volatile("cp.async.commit_group;" ::: "memory");
}
__device__ __forceinline__ void cp_wait0() {
    asm volatile("cp.async.wait_group 0;" ::: "memory");
}
__device__ __forceinline__ uint32_t smem_u32(const void* p) {
    return (uint32_t)__cvta_generic_to_shared(p);
}
__device__ __forceinline__ void ldm4(uint32_t* r, uint32_t addr) {
    asm volatile("ldmatrix.sync.aligned.m8n8.x4.shared.b16 {%0,%1,%2,%3}, [%4];"
                 : "=r"(r[0]), "=r"(r[1]), "=r"(r[2]), "=r"(r[3]) : "r"(addr));
}
__device__ __forceinline__ void mma16816(float* c, const uint32_t* a,
                                         uint32_t b0, uint32_t b1) {
    asm volatile("mma.sync.aligned.m16n8k16.row.col.f32.bf16.bf16.f32 "
                 "{%0,%1,%2,%3}, {%4,%5,%6,%7}, {%8,%9}, {%0,%1,%2,%3};"
                 : "+f"(c[0]), "+f"(c[1]), "+f"(c[2]), "+f"(c[3])
                 : "r"(a[0]), "r"(a[1]), "r"(a[2]), "r"(a[3]), "r"(b0), "r"(b1));
}
__device__ __forceinline__ void bsplit(float x, unsigned short& h, unsigned short& l) {
    __nv_bfloat16 hb = __float2bfloat16_rn(x);
    h = __bfloat16_as_ushort(hb);
    l = __bfloat16_as_ushort(__float2bfloat16_rn(x - __bfloat162float(hb)));
}

// ---------------- fp32 -> bf16 hi/lo split converters ----------------
__global__ void cvt_all(const float* v, const float* a,
                        const float* w0, const float* w1, const float* w2,
                        const float* w3, const float* w4, const float* w5,
                        const float* w6, const float* w7)
{
    const float* srcs[10] = { v, a, w0, w1, w2, w3, w4, w5, w6, w7 };
    const long long offs[10] = { OFF_VIDEO, OFF_ACTION,
        OFF_W + 0 * WSZ, OFF_W + 1 * WSZ, OFF_W + 2 * WSZ, OFF_W + 3 * WSZ,
        OFF_W + 4 * WSZ, OFF_W + 5 * WSZ, OFF_W + 6 * WSZ, OFF_W + 7 * WSZ };
    const int cnts[10] = { 4194304, 32768, 1048576, 1048576, 1048576, 1048576,
                           1048576, 1048576, 1048576, 1048576 };
    const int z = blockIdx.y;
    const float4* src = (const float4*)srcs[z];
    ushort4* hi = (ushort4*)(g_bh + offs[z]);
    ushort4* lo = (ushort4*)(g_bl + offs[z]);
    const int n4 = cnts[z] >> 2;
    for (int i = blockIdx.x * blockDim.x + threadIdx.x; i < n4;
         i += gridDim.x * blockDim.x) {
        const float4 x = src[i];
        ushort4 h, l;
        bsplit(x.x, h.x, l.x); bsplit(x.y, h.y, l.y);
        bsplit(x.z, h.z, l.z); bsplit(x.w, h.w, l.w);
        hi[i] = h; lo[i] = l;
    }
}

__global__ void cvt_ctx()
{
    const float4* src = (const float4*)g_ctx;
    ushort4* hi = (ushort4*)(g_bh + OFF_CTX);
    ushort4* lo = (ushort4*)(g_bl + OFF_CTX);
    const int n4 = (BSZ * NTOT * HIDDEN) >> 2;
    for (int i = blockIdx.x * blockDim.x + threadIdx.x; i < n4;
         i += gridDim.x * blockDim.x) {
        const float4 x = src[i];
        ushort4 h, l;
        bsplit(x.x, h.x, l.x); bsplit(x.y, h.y, l.y);
        bsplit(x.z, h.z, l.z); bsplit(x.w, h.w, l.w);
        hi[i] = h; lo[i] = l;
    }
}

// ================= mma.sync bf16x3 GEMM =================
// CTA: 128x128 tile, K=1024 in 16 chunks of 64 (bf16), double-buffered smem.
// 8 warps 2x4 (M x N); warp tile 64x32; D += Ah*Wh + Ah*Wl + Al*Wh.
#define GT_TILE 16384                 // one bf16 tile: 128 rows * 128 bytes
#define GT_BUF  (4 * GT_TILE)         // Ah, Al, Wh, Wl
#define GT_SMEM (2 * GT_BUF)          // 128 KB

__device__ __forceinline__ void gstage(const unsigned short* Ah, const unsigned short* Al,
                                       int M, int rowTile,
                                       const unsigned short* Wh, const unsigned short* Wl,
                                       int colTile, int k0, uint32_t bufb, int tid)
{
#pragma unroll
    for (int i = 0; i < 16; i++) {
        const int tile = i >> 2;
        const int t = ((i & 3) << 8) + tid;     // 0..1023
        const int row = t >> 3, c = t & 7;
        const uint32_t dst = bufb + tile * GT_TILE + (row << 7) + ((c ^ (row & 7)) << 4);
        if (tile == 0 || tile == 1) {
            const int m = rowTile + row;
            const int mm = (m < M) ? m : 0;
            const unsigned short* s = (tile == 0 ? Ah : Al) + (long long)mm * 1024 + k0 + c * 8;
            cpa16z(dst, s, (m < M) ? 16 : 0);
        } else {
            const unsigned short* s = (tile == 2 ? Wh : Wl) +
                                      (long long)(colTile + row) * 1024 + k0 + c * 8;
            cpa16z(dst, s, 16);
        }
    }
}

// MODE 0: out[m*1024+n]; MODE 1: qkv video scatter; MODE 2: qkv action scatter
template <int MODE>
__device__ __forceinline__ void gemm_body(const unsigned short* Ah, const unsigned short* Al,
                                          int M, int rowTile,
                                          const unsigned short* Wh, const unsigned short* Wl,
                                          int colTile, const float* bias,
                                          float* __restrict__ out)
{
    extern __shared__ char dsmem[];
    const uint32_t sbase = smem_u32(dsmem);
    const int tid = threadIdx.x;
    const int lane = tid & 31, wid = tid >> 5;
    const int warp_m = wid >> 2, warp_n = wid & 3;

    float acc[4][4][4];
#pragma unroll
    for (int a = 0; a < 4; a++)
#pragma unroll
        for (int b = 0; b < 4; b++)
#pragma unroll
            for (int c = 0; c < 4; c++) acc[a][b][c] = 0.f;

    int rA[4], rW[2];
#pragma unroll
    for (int mt = 0; mt < 4; mt++) rA[mt] = warp_m * 64 + mt * 16 + (lane & 15);
#pragma unroll
    for (int nt2 = 0; nt2 < 2; nt2++) rW[nt2] = warp_n * 32 + nt2 * 16 + (lane & 15);
    const int khalf = lane >> 4;

    gstage(Ah, Al, M, rowTile, Wh, Wl, colTile, 0, sbase, tid);
    cp_commit();

    for (int c = 0; c < 16; c++) {
        if (c + 1 < 16) {
            gstage(Ah, Al, M, rowTile, Wh, Wl, colTile, (c + 1) * 64,
                   sbase + ((c + 1) & 1) * GT_BUF, tid);
            cp_commit();
            asm volatile("cp.async.wait_group 1;" ::: "memory");
        } else {
            asm volatile("cp.async.wait_group 0;" ::: "memory");
        }
        __syncthreads();

        const uint32_t bufb = sbase + (c & 1) * GT_BUF;
        const uint32_t sAh = bufb, sAl = bufb + GT_TILE;
        const uint32_t sWh = bufb + 2 * GT_TILE, sWl = bufb + 3 * GT_TILE;

#pragma unroll
        for (int kq = 0; kq < 4; kq++) {
            const int kp = 2 * kq + khalf;
            uint32_t ah[4][4], al[4][4], wh[2][4], wl[2][4];
#pragma unroll
            for (int mt = 0; mt < 4; mt++) {
                const uint32_t off = (rA[mt] << 7) + ((kp ^ (rA[mt] & 7)) << 4);
                ldm4(ah[mt], sAh + off);
                ldm4(al[mt], sAl + off);
            }
#pragma unroll
            for (int nt2 = 0; nt2 < 2; nt2++) {
                const uint32_t off = (rW[nt2] << 7) + ((kp ^ (rW[nt2] & 7)) << 4);
                ldm4(wh[nt2], sWh + off);
                ldm4(wl[nt2], sWl + off);
            }
#pragma unroll
            for (int mt = 0; mt < 4; mt++) {
#pragma unroll
                for (int nt = 0; nt < 4; nt++) {
                    const uint32_t bh0 = wh[nt >> 1][nt & 1], bh1 = wh[nt >> 1][(nt & 1) + 2];
                    const uint32_t bl0 = wl[nt >> 1][nt & 1], bl1 = wl[nt >> 1][(nt & 1) + 2];
                    mma16816(acc[mt][nt], ah[mt], bh0, bh1);
                    mma16816(acc[mt][nt], ah[mt], bl0, bl1);
                    mma16816(acc[mt][nt], al[mt], bh0, bh1);
                }
            }
        }
        __syncthreads();
    }

    // epilogue
    const int g = lane >> 2, tg = lane & 3;
#pragma unroll
    for (int mt = 0; mt < 4; mt++) {
#pragma unroll
        for (int nt = 0; nt < 4; nt++) {
            const int n0 = colTile + warp_n * 32 + nt * 8 + tg * 2;
            const float2 bv = *(const float2*)(bias + n0);
#pragma unroll
            for (int hf = 0; hf < 2; hf++) {
                const int m = rowTile + warp_m * 64 + mt * 16 + g + hf * 8;
                if (m < M) {
                    float2 o;
                    o.x = acc[mt][nt][hf * 2 + 0] + bv.x;
                    o.y = acc[mt][nt][hf * 2 + 1] + bv.y;
                    if (MODE == 0) {
                        *(float2*)(out + (long long)m * 1024 + n0) = o;
                    } else if (MODE == 1) {
                        const int b_ = m >> 11, nn = m & 2047, h = n0 >> 6, d = n0 & 63;
                        *(float2*)(out + (((long long)(b_ * HEADS + h)) * NTOT + nn) * HD + d) = o;
                    } else {
                        const int b_ = m >> 4, h = n0 >> 6, d = n0 & 63;
                        const int nn = NVID + (m & 15);
                        *(float2*)(out + (((long long)(b_ * HEADS + h)) * NTOT + nn) * HD + d) = o;
                    }
                }
            }
        }
    }
}

// grid (8, 33, 3): z = {q,k,v}; by<32 video rows; by==32 action rows
__global__ __launch_bounds__(256, 1)
void gemm_qkv_mma(const float* bq, const float* bk, const float* bv,
                  const float* bqa, const float* bka, const float* bva)
{
    const int z = blockIdx.z;
    const bool act = (blockIdx.y == 32);
    const unsigned short* Ah = g_bh + (act ? OFF_ACTION : OFF_VIDEO);
    const unsigned short* Al = g_bl + (act ? OFF_ACTION : OFF_VIDEO);
    const int M = act ? (BSZ * NACT) : (BSZ * NVID);
    const int rowTile = act ? 0 : blockIdx.y * 128;
    const int colTile = blockIdx.x * 128;
    const int widx = z + (act ? 3 : 0);      // wq,wk,wv / wqa,wka,wva
    const unsigned short* Wh = g_bh + OFF_W + widx * WSZ;
    const unsigned short* Wl = g_bl + OFF_W + widx * WSZ;
    const float* bias = act ? (z == 0 ? bqa : (z == 1 ? bka : bva))
                            : (z == 0 ? bq : (z == 1 ? bk : bv));
    float* out = (z == 0) ? g_q : (z == 1 ? g_k : g_v);
    if (act) gemm_body<2>(Ah, Al, M, rowTile, Wh, Wl, colTile, bias, out);
    else     gemm_body<1>(Ah, Al, M, rowTile, Wh, Wl, colTile, bias, out);
}

// grid (8, 17, 2): z = batch; by<16 video rows; by==16 action rows
__global__ __launch_bounds__(256, 1)
void gemm_out_mma(const float* bp, const float* bpa, float* __restrict__ dout)
{
    const int z = blockIdx.z;
    const bool act = (blockIdx.y == 16);
    const long long aoff = OFF_CTX + (long long)z * NTOT * HIDDEN +
                           (act ? (long long)NVID * HIDDEN : 0);
    const unsigned short* Ah = g_bh + aoff;
    const unsigned short* Al = g_bl + aoff;
    const int M = act ? NACT : NVID;
    const int rowTile = act ? 0 : blockIdx.y * 128;
    const int colTile = blockIdx.x * 128;
    const int widx = act ? 7 : 6;
    const unsigned short* Wh = g_bh + OFF_W + widx * WSZ;
    const unsigned short* Wl = g_bl + OFF_W + widx * WSZ;
    const float* bias = act ? bpa : bp;
    float* C = act ? (dout + (long long)BSZ * NVID * HIDDEN + (long long)z * NACT * HIDDEN)
                   : (dout + (long long)z * NVID * HIDDEN);
    gemm_body<0>(Ah, Al, M, rowTile, Wh, Wl, colTile, bias, C);
}

// ---------------- RoPE (video tokens only; action positions are all 0 => identity) ----
__global__ void rope_kernel(float* __restrict__ q, float* __restrict__ k)
{
    const int TOT = BH * NVID * 30;
    int idx = blockIdx.x * blockDim.x + threadIdx.x;
    if (idx >= TOT) return;
    const int j = idx % 30;
    const int rest = idx / 30;
    const int n = rest & (NVID - 1);
    const int bh = rest >> 11;
    const int seg = j / 10, jj = j - seg * 10;
    const int pos = (seg == 0) ? (n >> 8) : (seg == 1 ? ((n >> 4) & 15) : (n & 15));
    const float omega = expf(-(float)jj * 0.1f * 9.210340371976184f);
    const float ang = (float)pos * omega;
    float s, c;
    sincosf(ang, &s, &c);
    const long long base = ((long long)bh * NTOT + n) * HD + seg * 20 + 2 * jj;
    float x1 = q[base], x2 = q[base + 1];
    q[base]     = x1 * c - x2 * s;
    q[base + 1] = x2 * c + x1 * s;
    x1 = k[base]; x2 = k[base + 1];
    k[base]     = x1 * c - x2 * s;
    k[base + 1] = x2 * c + x1 * s;
}

// ---------------- flash attention (unchanged, known-good) ----------------
#define STR 68
#define ATTN_SMEM_BYTES (6 * 64 * STR * 4)

__global__ __launch_bounds__(256, 2)
void attn_kernel(const float* __restrict__ Q, const float* __restrict__ K,
                 const float* __restrict__ V, float* __restrict__ ctx)
{
    extern __shared__ float smem[];
    float* sQ  = smem;
    float* sK0 = sQ  + 64 * STR;
    float* sK1 = sK0 + 64 * STR;
    float* sV0 = sK1 + 64 * STR;
    float* sV1 = sV0 + 64 * STR;
    float* sS  = sV1 + 64 * STR;

    const int tid = threadIdx.x;
    const int qt = blockIdx.x;
    const int bh = blockIdx.y;
    const int b = bh >> 4, h = bh & 15;
    const long long base = (long long)bh * NTOT * HD;
    const int ty = tid >> 4, tx = tid & 15;

#pragma unroll
    for (int t = 0; t < 4; t++) {
        const int lin = tid + t * 256;
        const int row = lin >> 4, c4 = (lin & 15) * 4;
        const int n = qt * 64 + row;
        if (n < NTOT) cpa16(&sQ[row * STR + c4], Q + base + (long long)n * HD + c4);
        cpa16(&sK0[row * STR + c4], K + base + (long long)row * HD + c4);
        cpa16(&sV0[row * STR + c4], V + base + (long long)row * HD + c4);
    }
    cp_commit();

    float rm[4], rl[4];
    F2 o2[4][2];
#pragma unroll
    for (int i = 0; i < 4; i++) {
        rm[i] = -1e30f; rl[i] = 0.f;
        o2[i][0].u = 0ull; o2[i][1].u = 0ull;
    }

    cp_wait0();
    __syncthreads();

    const int NKT = (NTOT + 63) / 64;
    for (int kt = 0; kt < NKT; kt++) {
        float* sK  = (kt & 1) ? sK1 : sK0;
        float* sV  = (kt & 1) ? sV1 : sV0;
        float* sKn = (kt & 1) ? sK0 : sK1;
        float* sVn = (kt & 1) ? sV0 : sV1;

        if (kt + 1 < NKT) {
#pragma unroll
            for (int t = 0; t < 4; t++) {
                const int lin = tid + t * 256;
                const int row = lin >> 4, c4 = (lin & 15) * 4;
                const int key = (kt + 1) * 64 + row;
                if (key < NTOT) {
                    cpa16(&sKn[row * STR + c4], K + base + (long long)key * HD + c4);
                    cpa16(&sVn[row * STR + c4], V + base + (long long)key * HD + c4);
                }
            }
        }
        cp_commit();

        F2 acc[4][2];
#pragma unroll
        for (int i = 0; i < 4; i++) { acc[i][0].u = 0ull; acc[i][1].u = 0ull; }
        for (int kk = 0; kk < 64; kk += 4) {
            Fl4 q4[4], k4[4];
#pragma unroll
            for (int i = 0; i < 4; i++)
                q4[i].v = *(const float4*)&sQ[(ty * 4 + i) * STR + kk];
#pragma unroll
            for (int c = 0; c < 4; c++)
                k4[c].v = *(const float4*)&sK[(tx + 16 * c) * STR + kk];
#pragma unroll
            for (int m = 0; m < 4; m++) {
                const unsigned long long kp0 = pack2(k4[0].s[m], k4[1].s[m]);
                const unsigned long long kp1 = pack2(k4[2].s[m], k4[3].s[m]);
#pragma unroll
                for (int i = 0; i < 4; i++) {
                    const unsigned long long qd = pack2(q4[i].s[m], q4[i].s[m]);
                    acc[i][0].u = ffma2(qd, kp0, acc[i][0].u);
                    acc[i][1].u = ffma2(qd, kp1, acc[i][1].u);
                }
            }
        }

        const int kvalid = NTOT - kt * 64;
#pragma unroll
        for (int i = 0; i < 4; i++) {
            float s0 = acc[i][0].f.x * ATT_SCALE;
            float s1 = acc[i][0].f.y * ATT_SCALE;
            float s2 = acc[i][1].f.x * ATT_SCALE;
            float s3 = acc[i][1].f.y * ATT_SCALE;
            if (kvalid < 64) {
                if (tx      >= kvalid) s0 = -1e30f;
                if (tx + 16 >= kvalid) s1 = -1e30f;
                if (tx + 32 >= kvalid) s2 = -1e30f;
                if (tx + 48 >= kvalid) s3 = -1e30f;
            }
            float tm = fmaxf(fmaxf(s0, s1), fmaxf(s2, s3));
#pragma unroll
            for (int o = 1; o < 16; o <<= 1)
                tm = fmaxf(tm, __shfl_xor_sync(0xffffffffu, tm, o));
            const float mnew = fmaxf(rm[i], tm);
            const float corr = __expf(rm[i] - mnew);
            rm[i] = mnew;
            const float p0 = __expf(s0 - mnew);
            const float p1 = __expf(s1 - mnew);
            const float p2 = __expf(s2 - mnew);
            const float p3 = __expf(s3 - mnew);
            float ts = (p0 + p1) + (p2 + p3);
#pragma unroll
            for (int o = 1; o < 16; o <<= 1)
                ts += __shfl_xor_sync(0xffffffffu, ts, o);
            rl[i] = rl[i] * corr + ts;
            o2[i][0].f.x *= corr; o2[i][0].f.y *= corr;
            o2[i][1].f.x *= corr; o2[i][1].f.y *= corr;
            float* prow = &sS[(ty * 4 + i) * STR];
            prow[tx] = p0; prow[tx + 16] = p1; prow[tx + 32] = p2; prow[tx + 48] = p3;
        }

        cp_wait0();
        __syncthreads();

        for (int kk = 0; kk < 64; kk += 4) {
            Fl4 p4[4], v4[4];
#pragma unroll
            for (int i = 0; i < 4; i++)
                p4[i].v = *(const float4*)&sS[(ty * 4 + i) * STR + kk];
#pragma unroll
            for (int m = 0; m < 4; m++)
                v4[m].v = *(const float4*)&sV[(kk + m) * STR + tx * 4];
#pragma unroll
            for (int m = 0; m < 4; m++) {
#pragma unroll
                for (int i = 0; i < 4; i++) {
                    const unsigned long long pd = pack2(p4[i].s[m], p4[i].s[m]);
                    o2[i][0].u = ffma2(pd, v4[m].u[0], o2[i][0].u);
                    o2[i][1].u = ffma2(pd, v4[m].u[1], o2[i][1].u);
                }
            }
        }
        __syncthreads();
    }

#pragma unroll
    for (int i = 0; i < 4; i++) {
        const int n = qt * 64 + ty * 4 + i;
        if (n < NTOT) {
            const float invl = 1.0f / rl[i];
            float4 ov;
            ov.x = o2[i][0].f.x * invl;
            ov.y = o2[i][0].f.y * invl;
            ov.z = o2[i][1].f.x * invl;
            ov.w = o2[i][1].f.y * invl;
            *(float4*)(ctx + ((long long)b * NTOT + n) * HIDDEN + h * HD + tx * 4) = ov;
        }
    }
}

// ---------------- host launcher ----------------
extern "C" void kernel_launch(void* const* d_in, const int* in_sizes, int n_in,
                              void* d_out, int out_size)
{
    (void)out_size;
    const float* video = nullptr;
    const float* action = nullptr;
    const float* wb[16];
    int wi = 0;
    for (int i = 0; i < n_in; i++) {
        const int sz = in_sizes[i];
        if (sz == BSZ * NVID * HIDDEN)       video  = (const float*)d_in[i];
        else if (sz == BSZ * NACT * HIDDEN)  action = (const float*)d_in[i];
        else if (wi < 16)                    wb[wi++] = (const float*)d_in[i];
    }
    float* out = (float*)d_out;

    float *qp, *kp, *vp, *cp;
    cudaGetSymbolAddress((void**)&qp, g_q);
    cudaGetSymbolAddress((void**)&kp, g_k);
    cudaGetSymbolAddress((void**)&vp, g_v);
    cudaGetSymbolAddress((void**)&cp, g_ctx);

    cudaFuncSetAttribute(gemm_qkv_mma, cudaFuncAttributeMaxDynamicSharedMemorySize, GT_SMEM);
    cudaFuncSetAttribute(gemm_out_mma, cudaFuncAttributeMaxDynamicSharedMemorySize, GT_SMEM);
    cudaFuncSetAttribute(attn_kernel, cudaFuncAttributeMaxDynamicSharedMemorySize,
                         ATTN_SMEM_BYTES);

    // split inputs + weights into bf16 hi/lo
    cvt_all<<<dim3(1024, 10), 256>>>(video, action, wb[0], wb[2], wb[4], wb[6],
                                     wb[8], wb[10], wb[12], wb[14]);

    // QKV projections on tensor cores (mma.sync bf16x3)
    gemm_qkv_mma<<<dim3(8, 33, 3), 256, GT_SMEM>>>(wb[1], wb[3], wb[5],
                                                   wb[7], wb[9], wb[11]);

    // RoPE on video q/k (action positions are all zero -> identity)
    const int tot = BH * NVID * 30;
    rope_kernel<<<(tot + 255) / 256, 256>>>(qp, kp);

    // attention (FFMA2 flash kernel)
    attn_kernel<<<dim3(33, 32), 256, ATTN_SMEM_BYTES>>>(qp, kp, vp, cp);

    // split ctx, then output projection on tensor cores
    cvt_ctx<<<2048, 256>>>();
    gemm_out_mma<<<dim3(8, 17, 2), 256, GT_SMEM>>>(wb[13], wb[15], out);
}

// round 6
// speedup vs baseline: 3.5116x; 1.9313x over previous
#include <cuda_runtime.h>
#include <cuda_bf16.h>
#include <cstdint>

#define HIDDEN 1024
#define HEADS 16
#define HD 64
#define NVID 2048
#define NACT 16
#define NTOT 2064
#define BSZ 2
#define BH (BSZ*HEADS)
// q pre-scale: ATT_SCALE * log2(e), so softmax uses exp2
#define QSC 0.18033688011112042f

#define WSZ 1048576LL
#define OFF_VIDEO 0LL
#define OFF_ACTION 4194304LL
#define OFF_W 4227072LL
#define OFF_CTX (OFF_W + 8LL * WSZ)
#define BF_TOTAL (OFF_CTX + 4227072LL)

// ---------------- scratch (device globals; no allocation allowed) ----------------
__device__ unsigned short g_bh[BF_TOTAL];    // bf16 hi: inputs, weights, ctx
__device__ unsigned short g_bl[BF_TOTAL];    // bf16 lo
__device__ unsigned short g_qh[BH * NTOT * HD], g_ql[BH * NTOT * HD];
__device__ unsigned short g_kh[BH * NTOT * HD], g_kl[BH * NTOT * HD];
__device__ unsigned short g_vh[BH * NTOT * HD], g_vl[BH * NTOT * HD];

// ---------------- helpers ----------------
__device__ __forceinline__ void cpa16z(uint32_t dst, const void* src, int bytes) {
    asm volatile("cp.async.cg.shared.global [%0], [%1], 16, %2;"
                 :: "r"(dst), "l"(src), "r"(bytes) : "memory");
}
__device__ __forceinline__ void cp_commit() {
    asm volatile("cp.async.commit_group;" ::: "memory");
}
__device__ __forceinline__ uint32_t smem_u32(const void* p) {
    return (uint32_t)__cvta_generic_to_shared(p);
}
__device__ __forceinline__ void ldm4(uint32_t* r, uint32_t addr) {
    asm volatile("ldmatrix.sync.aligned.m8n8.x4.shared.b16 {%0,%1,%2,%3}, [%4];"
                 : "=r"(r[0]), "=r"(r[1]), "=r"(r[2]), "=r"(r[3]) : "r"(addr));
}
__device__ __forceinline__ void ldm4t(uint32_t* r, uint32_t addr) {
    asm volatile("ldmatrix.sync.aligned.m8n8.x4.trans.shared.b16 {%0,%1,%2,%3}, [%4];"
                 : "=r"(r[0]), "=r"(r[1]), "=r"(r[2]), "=r"(r[3]) : "r"(addr));
}
__device__ __forceinline__ void mma16816(float* c, const uint32_t* a,
                                         uint32_t b0, uint32_t b1) {
    asm volatile("mma.sync.aligned.m16n8k16.row.col.f32.bf16.bf16.f32 "
                 "{%0,%1,%2,%3}, {%4,%5,%6,%7}, {%8,%9}, {%0,%1,%2,%3};"
                 : "+f"(c[0]), "+f"(c[1]), "+f"(c[2]), "+f"(c[3])
                 : "r"(a[0]), "r"(a[1]), "r"(a[2]), "r"(a[3]), "r"(b0), "r"(b1));
}
__device__ __forceinline__ void bsplit(float x, unsigned short& h, unsigned short& l) {
    __nv_bfloat16 hb = __float2bfloat16_rn(x);
    h = __bfloat16_as_ushort(hb);
    l = __bfloat16_as_ushort(__float2bfloat16_rn(x - __bfloat162float(hb)));
}
__device__ __forceinline__ uint32_t pkbf(float lo, float hi) {
    uint32_t r;
    asm("cvt.rn.bf16x2.f32 %0, %1, %2;" : "=r"(r) : "f"(hi), "f"(lo));
    return r;
}
__device__ __forceinline__ float ex2f(float x) {
    float y; asm("ex2.approx.ftz.f32 %0, %1;" : "=f"(y) : "f"(x)); return y;
}

// ---------------- fp32 -> bf16 hi/lo split (inputs + weights) ----------------
__global__ void cvt_all(const float* v, const float* a,
                        const float* w0, const float* w1, const float* w2,
                        const float* w3, const float* w4, const float* w5,
                        const float* w6, const float* w7)
{
    const float* srcs[10] = { v, a, w0, w1, w2, w3, w4, w5, w6, w7 };
    const long long offs[10] = { OFF_VIDEO, OFF_ACTION,
        OFF_W + 0 * WSZ, OFF_W + 1 * WSZ, OFF_W + 2 * WSZ, OFF_W + 3 * WSZ,
        OFF_W + 4 * WSZ, OFF_W + 5 * WSZ, OFF_W + 6 * WSZ, OFF_W + 7 * WSZ };
    const int cnts[10] = { 4194304, 32768, 1048576, 1048576, 1048576, 1048576,
                           1048576, 1048576, 1048576, 1048576 };
    const int z = blockIdx.y;
    const float4* src = (const float4*)srcs[z];
    ushort4* hi = (ushort4*)(g_bh + offs[z]);
    ushort4* lo = (ushort4*)(g_bl + offs[z]);
    const int n4 = cnts[z] >> 2;
    for (int i = blockIdx.x * blockDim.x + threadIdx.x; i < n4;
         i += gridDim.x * blockDim.x) {
        const float4 x = src[i];
        ushort4 h, l;
        bsplit(x.x, h.x, l.x); bsplit(x.y, h.y, l.y);
        bsplit(x.z, h.z, l.z); bsplit(x.w, h.w, l.w);
        hi[i] = h; lo[i] = l;
    }
}

// ================= mma.sync bf16x3 GEMM (projections) =================
#define GT_TILE 16384
#define GT_BUF  (4 * GT_TILE)
#define GT_SMEM (2 * GT_BUF)

__device__ __forceinline__ void gstage(const unsigned short* Ah, const unsigned short* Al,
                                       int M, int rowTile,
                                       const unsigned short* Wh, const unsigned short* Wl,
                                       int colTile, int k0, uint32_t bufb, int tid)
{
#pragma unroll
    for (int i = 0; i < 16; i++) {
        const int tile = i >> 2;
        const int t = ((i & 3) << 8) + tid;
        const int row = t >> 3, c = t & 7;
        const uint32_t dst = bufb + tile * GT_TILE + (row << 7) + ((c ^ (row & 7)) << 4);
        if (tile == 0 || tile == 1) {
            const int m = rowTile + row;
            const int mm = (m < M) ? m : 0;
            const unsigned short* s = (tile == 0 ? Ah : Al) + (long long)mm * 1024 + k0 + c * 8;
            cpa16z(dst, s, (m < M) ? 16 : 0);
        } else {
            const unsigned short* s = (tile == 2 ? Wh : Wl) +
                                      (long long)(colTile + row) * 1024 + k0 + c * 8;
            cpa16z(dst, s, 16);
        }
    }
}

// MODE 0: fp32 out[m*1024+n];  MODE 1: video qkv split+rope;  MODE 2: action qkv split
template <int MODE>
__device__ __forceinline__ void gemm_body(const unsigned short* Ah, const unsigned short* Al,
                                          int M, int rowTile,
                                          const unsigned short* Wh, const unsigned short* Wl,
                                          int colTile, const float* bias,
                                          float* __restrict__ outf,
                                          unsigned short* __restrict__ oh,
                                          unsigned short* __restrict__ ol, int rk)
{
    extern __shared__ char dsmem[];
    const uint32_t sbase = smem_u32(dsmem);
    const int tid = threadIdx.x;
    const int lane = tid & 31, wid = tid >> 5;
    const int warp_m = wid >> 2, warp_n = wid & 3;

    float acc[4][4][4];
#pragma unroll
    for (int a = 0; a < 4; a++)
#pragma unroll
        for (int b = 0; b < 4; b++)
#pragma unroll
            for (int c = 0; c < 4; c++) acc[a][b][c] = 0.f;

    int rA[4], rW[2];
#pragma unroll
    for (int mt = 0; mt < 4; mt++) rA[mt] = warp_m * 64 + mt * 16 + (lane & 15);
#pragma unroll
    for (int nt2 = 0; nt2 < 2; nt2++) rW[nt2] = warp_n * 32 + nt2 * 16 + (lane & 15);
    const int khalf = lane >> 4;

    gstage(Ah, Al, M, rowTile, Wh, Wl, colTile, 0, sbase, tid);
    cp_commit();

    for (int c = 0; c < 16; c++) {
        if (c + 1 < 16) {
            gstage(Ah, Al, M, rowTile, Wh, Wl, colTile, (c + 1) * 64,
                   sbase + ((c + 1) & 1) * GT_BUF, tid);
            cp_commit();
            asm volatile("cp.async.wait_group 1;" ::: "memory");
        } else {
            asm volatile("cp.async.wait_group 0;" ::: "memory");
        }
        __syncthreads();

        const uint32_t bufb = sbase + (c & 1) * GT_BUF;
        const uint32_t sAh = bufb, sAl = bufb + GT_TILE;
        const uint32_t sWh = bufb + 2 * GT_TILE, sWl = bufb + 3 * GT_TILE;

#pragma unroll
        for (int kq = 0; kq < 4; kq++) {
            const int kp = 2 * kq + khalf;
            uint32_t ah[4][4], al[4][4], wh[2][4], wl[2][4];
#pragma unroll
            for (int mt = 0; mt < 4; mt++) {
                const uint32_t off = (rA[mt] << 7) + ((kp ^ (rA[mt] & 7)) << 4);
                ldm4(ah[mt], sAh + off);
                ldm4(al[mt], sAl + off);
            }
#pragma unroll
            for (int nt2 = 0; nt2 < 2; nt2++) {
                const uint32_t off = (rW[nt2] << 7) + ((kp ^ (rW[nt2] & 7)) << 4);
                ldm4(wh[nt2], sWh + off);
                ldm4(wl[nt2], sWl + off);
            }
#pragma unroll
            for (int mt = 0; mt < 4; mt++) {
#pragma unroll
                for (int nt = 0; nt < 4; nt++) {
                    const uint32_t bh0 = wh[nt >> 1][nt & 1], bh1 = wh[nt >> 1][(nt & 1) + 2];
                    const uint32_t bl0 = wl[nt >> 1][nt & 1], bl1 = wl[nt >> 1][(nt & 1) + 2];
                    mma16816(acc[mt][nt], ah[mt], bh0, bh1);
                    mma16816(acc[mt][nt], ah[mt], bl0, bl1);
                    mma16816(acc[mt][nt], al[mt], bh0, bh1);
                }
            }
        }
        __syncthreads();
    }

    // epilogue
    const int g = lane >> 2, tg = lane & 3;
#pragma unroll
    for (int mt = 0; mt < 4; mt++) {
#pragma unroll
        for (int nt = 0; nt < 4; nt++) {
            const int n0 = colTile + warp_n * 32 + nt * 8 + tg * 2;
            const float2 bv = *(const float2*)(bias + n0);
#pragma unroll
            for (int hf = 0; hf < 2; hf++) {
                const int m = rowTile + warp_m * 64 + mt * 16 + g + hf * 8;
                if (m >= M) continue;
                float v0 = acc[mt][nt][hf * 2 + 0] + bv.x;
                float v1 = acc[mt][nt][hf * 2 + 1] + bv.y;
                if (MODE == 0) {
                    float2 o; o.x = v0; o.y = v1;
                    *(float2*)(outf + (long long)m * 1024 + n0) = o;
                } else {
                    int b_, nn;
                    if (MODE == 1) { b_ = m >> 11; nn = m & 2047; }
                    else           { b_ = m >> 4;  nn = NVID + (m & 15); }
                    const int hh = n0 >> 6, d = n0 & 63;
                    if (MODE == 1 && rk && d < 60) {
                        const int seg = d / 20, jj = (d - seg * 20) >> 1;
                        const int pos = (seg == 0) ? (nn >> 8)
                                      : (seg == 1) ? ((nn >> 4) & 15) : (nn & 15);
                        const float omega = ex2f(-(float)jj * 1.3287712379549449f);
                        float sn, cs;
                        sincosf((float)pos * omega, &sn, &cs);
                        const float x1 = v0 * cs - v1 * sn;
                        const float x2 = v1 * cs + v0 * sn;
                        v0 = x1; v1 = x2;
                    }
                    if (rk == 1) { v0 *= QSC; v1 *= QSC; }
                    unsigned short h0, l0_, h1, l1_;
                    bsplit(v0, h0, l0_); bsplit(v1, h1, l1_);
                    const long long idx = (((long long)(b_ * HEADS + hh)) * NTOT + nn) * HD + d;
                    *(ushort2*)(oh + idx) = make_ushort2(h0, h1);
                    *(ushort2*)(ol + idx) = make_ushort2(l0_, l1_);
                }
            }
        }
    }
}

// grid (8, 33, 3): z = {q,k,v}; by<32 video rows; by==32 action rows
__global__ __launch_bounds__(256, 1)
void gemm_qkv_mma(const float* bq, const float* bk, const float* bv,
                  const float* bqa, const float* bka, const float* bva)
{
    const int z = blockIdx.z;
    const bool act = (blockIdx.y == 32);
    const unsigned short* Ah = g_bh + (act ? OFF_ACTION : OFF_VIDEO);
    const unsigned short* Al = g_bl + (act ? OFF_ACTION : OFF_VIDEO);
    const int M = act ? (BSZ * NACT) : (BSZ * NVID);
    const int rowTile = act ? 0 : blockIdx.y * 128;
    const int colTile = blockIdx.x * 128;
    const int widx = z + (act ? 3 : 0);
    const unsigned short* Wh = g_bh + OFF_W + widx * WSZ;
    const unsigned short* Wl = g_bl + OFF_W + widx * WSZ;
    const float* bias = act ? (z == 0 ? bqa : (z == 1 ? bka : bva))
                            : (z == 0 ? bq : (z == 1 ? bk : bv));
    unsigned short *oh, *ol;
    int rk;
    if (z == 0)      { oh = g_qh; ol = g_ql; rk = 1; }
    else if (z == 1) { oh = g_kh; ol = g_kl; rk = 2; }
    else             { oh = g_vh; ol = g_vl; rk = 0; }
    if (act) gemm_body<2>(Ah, Al, M, rowTile, Wh, Wl, colTile, bias, nullptr, oh, ol, rk);
    else     gemm_body<1>(Ah, Al, M, rowTile, Wh, Wl, colTile, bias, nullptr, oh, ol, rk);
}

// grid (8, 17, 2): z = batch; by<16 video rows; by==16 action rows
__global__ __launch_bounds__(256, 1)
void gemm_out_mma(const float* bp, const float* bpa, float* __restrict__ dout)
{
    const int z = blockIdx.z;
    const bool act = (blockIdx.y == 16);
    const long long aoff = OFF_CTX + (long long)z * NTOT * HIDDEN +
                           (act ? (long long)NVID * HIDDEN : 0);
    const unsigned short* Ah = g_bh + aoff;
    const unsigned short* Al = g_bl + aoff;
    const int M = act ? NACT : NVID;
    const int rowTile = act ? 0 : blockIdx.y * 128;
    const int colTile = blockIdx.x * 128;
    const int widx = act ? 7 : 6;
    const unsigned short* Wh = g_bh + OFF_W + widx * WSZ;
    const unsigned short* Wl = g_bl + OFF_W + widx * WSZ;
    const float* bias = act ? bpa : bp;
    float* C = act ? (dout + (long long)BSZ * NVID * HIDDEN + (long long)z * NACT * HIDDEN)
                   : (dout + (long long)z * NVID * HIDDEN);
    gemm_body<0>(Ah, Al, M, rowTile, Wh, Wl, colTile, bias, C, nullptr, nullptr, 0);
}

// ================= flash attention on mma.sync =================
// CTA: 128 q-rows x full K sweep (17 tiles of 128 keys). 8 warps, 16 rows each.
#define AT_TILE 16384
#define AT_BUF0 32768
#define AT_BUF1 (32768 + 65536)
#define AT_SMEM (32768 + 2 * 65536)   // Qh+Ql + 2 KV buffers = 160 KB

__device__ __forceinline__ void stage_kv(const unsigned short* Kh, const unsigned short* Kl,
                                         const unsigned short* Vh, const unsigned short* Vl,
                                         long long base, int kt, uint32_t bufb, int tid)
{
#pragma unroll
    for (int i = 0; i < 16; i++) {
        const int arr = i >> 2;
        const int t = ((i & 3) << 8) + tid;
        const int row = t >> 3, c = t & 7;
        const int key = kt * 128 + row;
        const uint32_t dst = bufb + arr * AT_TILE + (row << 7) + ((c ^ (row & 7)) << 4);
        const unsigned short* s =
            (arr == 0 ? Kh : arr == 1 ? Kl : arr == 2 ? Vh : Vl) +
            base + (long long)(key < NTOT ? key : 0) * HD + c * 8;
        cpa16z(dst, s, (key < NTOT) ? 16 : 0);
    }
}

__global__ __launch_bounds__(256, 1)
void attn_mma()
{
    extern __shared__ char dsm[];
    const uint32_t sb = smem_u32(dsm);
    const int tid = threadIdx.x, lane = tid & 31, w = tid >> 5;
    const int qt = blockIdx.x, bh = blockIdx.y;
    const int b = bh >> 4, h = bh & 15;
    const long long base = (long long)bh * NTOT * HD;
    const int g = lane >> 2, tg = lane & 3;

    // stage Q (hi/lo) + KV tile 0 (group 0)
#pragma unroll
    for (int i = 0; i < 8; i++) {
        const int arr = i >> 2;
        const int t = ((i & 3) << 8) + tid;
        const int row = t >> 3, c = t & 7;
        const int n = qt * 128 + row;
        const uint32_t dst = sb + arr * AT_TILE + (row << 7) + ((c ^ (row & 7)) << 4);
        const unsigned short* src = (arr == 0 ? g_qh : g_ql) +
                                    base + (long long)(n < NTOT ? n : 0) * HD + c * 8;
        cpa16z(dst, src, (n < NTOT) ? 16 : 0);
    }
    stage_kv(g_kh, g_kl, g_vh, g_vl, base, 0, sb + AT_BUF0, tid);
    cp_commit();

    float oacc[8][4];
#pragma unroll
    for (int i = 0; i < 8; i++)
#pragma unroll
        for (int j = 0; j < 4; j++) oacc[i][j] = 0.f;
    float m0 = -1e30f, m1 = -1e30f, l0 = 0.f, l1 = 0.f;
    uint32_t qfh[4][4], qfl[4][4];

    const int NKT = 17;
    for (int kt = 0; kt < NKT; kt++) {
        if (kt + 1 < NKT) {
            stage_kv(g_kh, g_kl, g_vh, g_vl, base, kt + 1,
                     sb + (((kt + 1) & 1) ? AT_BUF1 : AT_BUF0), tid);
            cp_commit();
            asm volatile("cp.async.wait_group 1;" ::: "memory");
        } else {
            asm volatile("cp.async.wait_group 0;" ::: "memory");
        }
        __syncthreads();

        if (kt == 0) {   // Q fragments (once)
            const int row = w * 16 + (lane & 15);
#pragma unroll
            for (int kq = 0; kq < 4; kq++) {
                const int kp = 2 * kq + (lane >> 4);
                const uint32_t off = (row << 7) + ((kp ^ (row & 7)) << 4);
                ldm4(qfh[kq], sb + off);
                ldm4(qfl[kq], sb + AT_TILE + off);
            }
        }

        const uint32_t bufb = sb + ((kt & 1) ? AT_BUF1 : AT_BUF0);
        const uint32_t sKh = bufb, sKl = bufb + AT_TILE;
        const uint32_t sVh = bufb + 2 * AT_TILE, sVl = bufb + 3 * AT_TILE;

        float sacc[16][4];
#pragma unroll
        for (int i = 0; i < 16; i++)
#pragma unroll
            for (int j = 0; j < 4; j++) sacc[i][j] = 0.f;

        // S = Q K^T (bf16x3; Q pre-scaled by 0.125*log2e)
#pragma unroll
        for (int kq = 0; kq < 4; kq++) {
            const int kp = 2 * kq + (lane >> 4);
#pragma unroll
            for (int ng = 0; ng < 8; ng++) {
                const int row = ng * 16 + (lane & 15);
                const uint32_t off = (row << 7) + ((kp ^ (row & 7)) << 4);
                uint32_t kh4[4], kl4[4];
                ldm4(kh4, sKh + off);
                ldm4(kl4, sKl + off);
#pragma unroll
                for (int j = 0; j < 2; j++) {
                    mma16816(sacc[ng * 2 + j], qfh[kq], kh4[j], kh4[j + 2]);
                    mma16816(sacc[ng * 2 + j], qfh[kq], kl4[j], kl4[j + 2]);
                    mma16816(sacc[ng * 2 + j], qfl[kq], kh4[j], kh4[j + 2]);
                }
            }
        }

        // mask + online softmax (base-2)
        const int kvalid = NTOT - kt * 128;
        if (kvalid < 128) {
#pragma unroll
            for (int nt = 0; nt < 16; nt++) {
                const int c0 = nt * 8 + 2 * tg;
                if (c0 >= kvalid)     { sacc[nt][0] = -1e30f; sacc[nt][2] = -1e30f; }
                if (c0 + 1 >= kvalid) { sacc[nt][1] = -1e30f; sacc[nt][3] = -1e30f; }
            }
        }
        float mx0 = -1e30f, mx1 = -1e30f;
#pragma unroll
        for (int nt = 0; nt < 16; nt++) {
            mx0 = fmaxf(mx0, fmaxf(sacc[nt][0], sacc[nt][1]));
            mx1 = fmaxf(mx1, fmaxf(sacc[nt][2], sacc[nt][3]));
        }
        mx0 = fmaxf(mx0, __shfl_xor_sync(0xffffffffu, mx0, 1));
        mx0 = fmaxf(mx0, __shfl_xor_sync(0xffffffffu, mx0, 2));
        mx1 = fmaxf(mx1, __shfl_xor_sync(0xffffffffu, mx1, 1));
        mx1 = fmaxf(mx1, __shfl_xor_sync(0xffffffffu, mx1, 2));
        const float mn0 = fmaxf(m0, mx0), mn1 = fmaxf(m1, mx1);
        const float cr0 = ex2f(m0 - mn0), cr1 = ex2f(m1 - mn1);
        m0 = mn0; m1 = mn1;
        float s0 = 0.f, s1 = 0.f;
#pragma unroll
        for (int nt = 0; nt < 16; nt++) {
            sacc[nt][0] = ex2f(sacc[nt][0] - mn0);
            sacc[nt][1] = ex2f(sacc[nt][1] - mn0);
            sacc[nt][2] = ex2f(sacc[nt][2] - mn1);
            sacc[nt][3] = ex2f(sacc[nt][3] - mn1);
            s0 += sacc[nt][0] + sacc[nt][1];
            s1 += sacc[nt][2] + sacc[nt][3];
        }
        s0 += __shfl_xor_sync(0xffffffffu, s0, 1);
        s0 += __shfl_xor_sync(0xffffffffu, s0, 2);
        s1 += __shfl_xor_sync(0xffffffffu, s1, 1);
        s1 += __shfl_xor_sync(0xffffffffu, s1, 2);
        l0 = l0 * cr0 + s0; l1 = l1 * cr1 + s1;
#pragma unroll
        for (int nt = 0; nt < 8; nt++) {
            oacc[nt][0] *= cr0; oacc[nt][1] *= cr0;
            oacc[nt][2] *= cr1; oacc[nt][3] *= cr1;
        }

        // O += P V  (P split hi/lo, V split; drop lo*lo)
#pragma unroll
        for (int kc = 0; kc < 8; kc++) {
            uint32_t pah[4], pal[4];
            const float* t0 = sacc[2 * kc];
            const float* t1 = sacc[2 * kc + 1];
            pah[0] = pkbf(t0[0], t0[1]);
            pah[1] = pkbf(t0[2], t0[3]);
            pah[2] = pkbf(t1[0], t1[1]);
            pah[3] = pkbf(t1[2], t1[3]);
#pragma unroll
            for (int u = 0; u < 4; u++) {
                const float* tt = (u < 2) ? t0 : t1;
                const float e0 = tt[(u & 1) * 2 + 0] - __uint_as_float(pah[u] << 16);
                const float e1 = tt[(u & 1) * 2 + 1] - __uint_as_float(pah[u] & 0xFFFF0000u);
                pal[u] = pkbf(e0, e1);
            }
#pragma unroll
            for (int ng = 0; ng < 4; ng++) {
                const int row = kc * 16 + (lane & 15);
                const int cc = 2 * ng + (lane >> 4);
                const uint32_t off = (row << 7) + ((cc ^ (row & 7)) << 4);
                uint32_t vh4[4], vl4[4];
                ldm4t(vh4, sVh + off);
                ldm4t(vl4, sVl + off);
#pragma unroll
                for (int j = 0; j < 2; j++) {
                    mma16816(oacc[ng * 2 + j], pah, vh4[2 * j], vh4[2 * j + 1]);
                    mma16816(oacc[ng * 2 + j], pah, vl4[2 * j], vl4[2 * j + 1]);
                    mma16816(oacc[ng * 2 + j], pal, vh4[2 * j], vh4[2 * j + 1]);
                }
            }
        }
        __syncthreads();
    }

    // normalize + write ctx as bf16 hi/lo split (consumed by out-proj)
    const float iv0 = 1.f / l0, iv1 = 1.f / l1;
    const int n0 = qt * 128 + w * 16 + g;
    const int n1 = n0 + 8;
#pragma unroll
    for (int nt = 0; nt < 8; nt++) {
        const int d = nt * 8 + 2 * tg;
        if (n0 < NTOT) {
            unsigned short h0, l0_, h1, l1_;
            bsplit(oacc[nt][0] * iv0, h0, l0_);
            bsplit(oacc[nt][1] * iv0, h1, l1_);
            const long long idx = OFF_CTX + ((long long)(b * NTOT + n0)) * HIDDEN + h * HD + d;
            *(ushort2*)(g_bh + idx) = make_ushort2(h0, h1);
            *(ushort2*)(g_bl + idx) = make_ushort2(l0_, l1_);
        }
        if (n1 < NTOT) {
            unsigned short h0, l0_, h1, l1_;
            bsplit(oacc[nt][2] * iv1, h0, l0_);
            bsplit(oacc[nt][3] * iv1, h1, l1_);
            const long long idx = OFF_CTX + ((long long)(b * NTOT + n1)) * HIDDEN + h * HD + d;
            *(ushort2*)(g_bh + idx) = make_ushort2(h0, h1);
            *(ushort2*)(g_bl + idx) = make_ushort2(l0_, l1_);
        }
    }
}

// ---------------- host launcher ----------------
extern "C" void kernel_launch(void* const* d_in, const int* in_sizes, int n_in,
                              void* d_out, int out_size)
{
    (void)out_size;
    const float* video = nullptr;
    const float* action = nullptr;
    const float* wb[16];
    int wi = 0;
    for (int i = 0; i < n_in; i++) {
        const int sz = in_sizes[i];
        if (sz == BSZ * NVID * HIDDEN)       video  = (const float*)d_in[i];
        else if (sz == BSZ * NACT * HIDDEN)  action = (const float*)d_in[i];
        else if (wi < 16)                    wb[wi++] = (const float*)d_in[i];
    }
    float* out = (float*)d_out;

    cudaFuncSetAttribute(gemm_qkv_mma, cudaFuncAttributeMaxDynamicSharedMemorySize, GT_SMEM);
    cudaFuncSetAttribute(gemm_out_mma, cudaFuncAttributeMaxDynamicSharedMemorySize, GT_SMEM);
    cudaFuncSetAttribute(attn_mma, cudaFuncAttributeMaxDynamicSharedMemorySize, AT_SMEM);

    // split inputs + weights into bf16 hi/lo
    cvt_all<<<dim3(1024, 10), 256>>>(video, action, wb[0], wb[2], wb[4], wb[6],
                                     wb[8], wb[10], wb[12], wb[14]);

    // QKV projections (rope + scale + split fused in epilogue)
    gemm_qkv_mma<<<dim3(8, 33, 3), 256, GT_SMEM>>>(wb[1], wb[3], wb[5],
                                                   wb[7], wb[9], wb[11]);

    // attention on tensor cores
    attn_mma<<<dim3(17, 32), 256, AT_SMEM>>>();

    // output projection
    gemm_out_mma<<<dim3(8, 17, 2), 256, GT_SMEM>>>(wb[13], wb[15], out);
}